// round 1
// baseline (speedup 1.0000x reference)
#include <cuda_runtime.h>
#include <math.h>

// Problem constants
#define BB   2
#define SS   2048
#define DD   1024
#define HH   16
#define HS   64

// Scratch (device globals: allocation-free rule)
__device__ float g_Qt[BB * DD * SS];   // [b][h*64+d][s]  (d-major for attention)
__device__ float g_Kt[BB * DD * SS];   // [b][h*64+d][s]
__device__ float g_V [BB * SS * DD];   // [b*S+s][n]      (natural)
__device__ float g_At[BB * SS * DD];   // attention out, natural

// ---------------------------------------------------------------------------
// SGEMM: C = A[4096,1024] @ W[1024,1024] + bias
// TRANSOUT=0: C[m][n] natural.  TRANSOUT=1: C[(b*1024+n)*2048 + s], m=b*2048+s.
// 128x128x16 block tile, 256 threads, 8x8 micro-tile (FMA:LDS balanced).
// ---------------------------------------------------------------------------
template <int TRANSOUT>
__global__ __launch_bounds__(256, 2)
void sgemm_bias_kernel(const float* __restrict__ A,
                       const float* __restrict__ W,
                       const float* __restrict__ bias,
                       float* __restrict__ C)
{
    const int Kd = DD, Nd = DD;
    __shared__ float As[16][132];   // A^T tile, padded (2-way store conflict only)
    __shared__ float Ws[16][128];

    const int tid = threadIdx.x;
    const int tx = tid & 15, ty = tid >> 4;
    const int m0 = blockIdx.y * 128;
    const int n0 = blockIdx.x * 128;

    const int arow = tid >> 2;          // 0..63
    const int acol = (tid & 3) << 2;    // 0,4,8,12
    const int wrow = tid >> 5;          // 0..7
    const int wcol = (tid & 31) << 2;   // 0..124

    float acc[8][8];
#pragma unroll
    for (int i = 0; i < 8; i++)
#pragma unroll
        for (int j = 0; j < 8; j++) acc[i][j] = 0.f;

    const float* Ap = A + (size_t)m0 * Kd;

    for (int k0 = 0; k0 < Kd; k0 += 16) {
#pragma unroll
        for (int r = 0; r < 2; r++) {
            float4 a = *(const float4*)(Ap + (size_t)(arow + r * 64) * Kd + k0 + acol);
            As[acol + 0][arow + r * 64] = a.x;
            As[acol + 1][arow + r * 64] = a.y;
            As[acol + 2][arow + r * 64] = a.z;
            As[acol + 3][arow + r * 64] = a.w;
        }
#pragma unroll
        for (int r = 0; r < 2; r++) {
            *(float4*)&Ws[wrow + r * 8][wcol] =
                *(const float4*)(W + (size_t)(k0 + wrow + r * 8) * Nd + n0 + wcol);
        }
        __syncthreads();

#pragma unroll
        for (int kk = 0; kk < 16; kk++) {
            float af[8], wf[8];
            *(float4*)&af[0] = *(const float4*)&As[kk][ty * 8];
            *(float4*)&af[4] = *(const float4*)&As[kk][ty * 8 + 4];
            *(float4*)&wf[0] = *(const float4*)&Ws[kk][tx * 4];        // cols tx*4..+3
            *(float4*)&wf[4] = *(const float4*)&Ws[kk][64 + tx * 4];   // cols 64+tx*4..
#pragma unroll
            for (int i = 0; i < 8; i++)
#pragma unroll
                for (int j = 0; j < 8; j++)
                    acc[i][j] = fmaf(af[i], wf[j], acc[i][j]);
        }
        __syncthreads();
    }

    if (TRANSOUT == 0) {
#pragma unroll
        for (int i = 0; i < 8; i++) {
            const int m = m0 + ty * 8 + i;
#pragma unroll
            for (int hhf = 0; hhf < 2; hhf++) {
                const int n = n0 + hhf * 64 + tx * 4;
                float4 bv = *(const float4*)(bias + n);
                float4 v = make_float4(acc[i][hhf * 4 + 0] + bv.x,
                                       acc[i][hhf * 4 + 1] + bv.y,
                                       acc[i][hhf * 4 + 2] + bv.z,
                                       acc[i][hhf * 4 + 3] + bv.w);
                *(float4*)(C + (size_t)m * Nd + n) = v;
            }
        }
    } else {
        const int b  = m0 >> 11;               // m0 / 2048
        const int s0 = (m0 & 2047) + ty * 8;
#pragma unroll
        for (int j = 0; j < 8; j++) {
            const int n = n0 + ((j < 4) ? (tx * 4 + j) : (64 + tx * 4 + (j - 4)));
            const float bb = bias[n];
            float* Cp = C + (((size_t)(b * 1024 + n)) << 11) + s0;
            float4 v0 = make_float4(acc[0][j] + bb, acc[1][j] + bb,
                                    acc[2][j] + bb, acc[3][j] + bb);
            float4 v1 = make_float4(acc[4][j] + bb, acc[5][j] + bb,
                                    acc[6][j] + bb, acc[7][j] + bb);
            *(float4*)(Cp)     = v0;
            *(float4*)(Cp + 4) = v1;
        }
    }
}

// ---------------------------------------------------------------------------
// Causal flash attention, fp32. BQ=BKV=128, HS=64, 256 threads (16x16),
// 8q x 8k score micro-tile, 8q x 4d output micro-tile. Online softmax.
// Qt/Kt are d-major [b][h*64+d][s]; V natural; output natural.
// smem: sQ 64x128, sK 64x128, sV 128x64, sP 128x128 (XOR-swizzled) = 160 KB.
// ---------------------------------------------------------------------------
__global__ __launch_bounds__(256, 1)
void flash_attn_kernel(const float* __restrict__ Qt,
                       const float* __restrict__ Kt,
                       const float* __restrict__ V,
                       float* __restrict__ O)
{
    extern __shared__ float sm[];
    float* sQ = sm;                 // [d][q]  64*128
    float* sK = sm + 8192;          // [d][k]  64*128
    float* sV = sm + 16384;         // [k][d]  128*64
    float* sP = sm + 24576;         // [k][q]  128*128, swizzled

    const int tid = threadIdx.x;
    const int tx = tid & 15, ty = tid >> 4;
    const int qt = (int)gridDim.x - 1 - (int)blockIdx.x;  // heavy blocks first
    const int qb = qt * 128;
    const int h  = blockIdx.y;
    const int b  = blockIdx.z;

    const float scale = 0.125f;     // 1/sqrt(64)

    const size_t headoff = ((size_t)(b * 1024 + h * 64)) << 11;  // *2048
    const float* Qg = Qt + headoff + qb;
    const float* Kg = Kt + headoff;
    const float* Vg = V + ((size_t)b << 21) + h * 64;            // b*2048*1024

    // Load Q tile (scaled), d-major
    {
        const int d0 = tid >> 5;            // 0..7
        const int c4 = (tid & 31) << 2;     // 0..124
#pragma unroll
        for (int it = 0; it < 8; it++) {
            const int dd = it * 8 + d0;
            float4 v = *(const float4*)(Qg + ((size_t)dd << 11) + c4);
            v.x *= scale; v.y *= scale; v.z *= scale; v.w *= scale;
            *(float4*)&sQ[dd * 128 + c4] = v;
        }
    }

    float m_i[8], l_i[8], Oa[8][4];
#pragma unroll
    for (int i = 0; i < 8; i++) {
        m_i[i] = -INFINITY; l_i[i] = 0.f;
#pragma unroll
        for (int c = 0; c < 4; c++) Oa[i][c] = 0.f;
    }

    const int nkt = qt + 1;
    for (int kt2 = 0; kt2 < nkt; kt2++) {
        const int kb = kt2 * 128;
        __syncthreads();   // previous iteration's smem reads (and Q fill) done

        // Load K tile, d-major
        {
            const int d0 = tid >> 5;
            const int c4 = (tid & 31) << 2;
#pragma unroll
            for (int it = 0; it < 8; it++) {
                const int dd = it * 8 + d0;
                *(float4*)&sK[dd * 128 + c4] =
                    *(const float4*)(Kg + ((size_t)dd << 11) + kb + c4);
            }
        }
        // Load V tile, natural [k][d]
        {
#pragma unroll
            for (int it = 0; it < 8; it++) {
                const int idx = it * 256 + tid;
                const int k  = idx >> 4;
                const int d4 = (idx & 15) << 2;
                *(float4*)&sV[k * 64 + d4] =
                    *(const float4*)(Vg + ((size_t)(kb + k) << 10) + d4);
            }
        }
        __syncthreads();

        // Scores: sc[i][j] = sum_d Q[q][d] K[k][d]
        float sc[8][8];
#pragma unroll
        for (int i = 0; i < 8; i++)
#pragma unroll
            for (int j = 0; j < 8; j++) sc[i][j] = 0.f;

#pragma unroll 8
        for (int d = 0; d < 64; d++) {
            float qf[8], kf[8];
            *(float4*)&qf[0] = *(const float4*)&sQ[d * 128 + ty * 8];
            *(float4*)&qf[4] = *(const float4*)&sQ[d * 128 + ty * 8 + 4];
            *(float4*)&kf[0] = *(const float4*)&sK[d * 128 + tx * 4];
            *(float4*)&kf[4] = *(const float4*)&sK[d * 128 + 64 + tx * 4];
#pragma unroll
            for (int i = 0; i < 8; i++)
#pragma unroll
                for (int j = 0; j < 8; j++)
                    sc[i][j] = fmaf(qf[i], kf[j], sc[i][j]);
        }

        // Causal mask (diagonal tile only)
        if (kt2 == qt) {
#pragma unroll
            for (int i = 0; i < 8; i++) {
                const int q = qb + ty * 8 + i;
#pragma unroll
                for (int j = 0; j < 8; j++) {
                    const int k = kb + ((j < 4) ? (tx * 4 + j) : (64 + tx * 4 + (j - 4)));
                    if (k > q) sc[i][j] = -INFINITY;
                }
            }
        }

        // Online softmax (rows shared by 16-lane tx group within half-warp)
#pragma unroll
        for (int i = 0; i < 8; i++) {
            float mx = sc[i][0];
#pragma unroll
            for (int j = 1; j < 8; j++) mx = fmaxf(mx, sc[i][j]);
            mx = fmaxf(mx, __shfl_xor_sync(0xffffffffu, mx, 1));
            mx = fmaxf(mx, __shfl_xor_sync(0xffffffffu, mx, 2));
            mx = fmaxf(mx, __shfl_xor_sync(0xffffffffu, mx, 4));
            mx = fmaxf(mx, __shfl_xor_sync(0xffffffffu, mx, 8));
            const float mn = fmaxf(m_i[i], mx);
            const float al = __expf(m_i[i] - mn);   // first iter: exp(-inf)=0
            m_i[i] = mn;
            float rs = 0.f;
#pragma unroll
            for (int j = 0; j < 8; j++) {
                sc[i][j] = __expf(sc[i][j] - mn);   // masked -> 0
                rs += sc[i][j];
            }
            rs += __shfl_xor_sync(0xffffffffu, rs, 1);
            rs += __shfl_xor_sync(0xffffffffu, rs, 2);
            rs += __shfl_xor_sync(0xffffffffu, rs, 4);
            rs += __shfl_xor_sync(0xffffffffu, rs, 8);
            l_i[i] = l_i[i] * al + rs;
#pragma unroll
            for (int c = 0; c < 4; c++) Oa[i][c] *= al;
        }

        // Store P^T to smem [k][q], XOR-swizzled column quads (conflict-free)
#pragma unroll
        for (int j = 0; j < 8; j++) {
            const int krow = (j < 4) ? (tx * 4 + j) : (64 + tx * 4 + (j - 4));
            const int swz = (krow >> 2) & 7;
            float4 v0 = make_float4(sc[0][j], sc[1][j], sc[2][j], sc[3][j]);
            float4 v1 = make_float4(sc[4][j], sc[5][j], sc[6][j], sc[7][j]);
            *(float4*)&sP[krow * 128 + (((2 * ty + 0) ^ swz) << 2)] = v0;
            *(float4*)&sP[krow * 128 + (((2 * ty + 1) ^ swz) << 2)] = v1;
        }
        __syncthreads();

        // PV: Oa[i][c] += P[q][k] * V[k][d]
#pragma unroll 4
        for (int k = 0; k < 128; k++) {
            const int swz = (k >> 2) & 7;
            float pf[8], vf[4];
            *(float4*)&pf[0] = *(const float4*)&sP[k * 128 + (((2 * ty + 0) ^ swz) << 2)];
            *(float4*)&pf[4] = *(const float4*)&sP[k * 128 + (((2 * ty + 1) ^ swz) << 2)];
            *(float4*)&vf[0] = *(const float4*)&sV[k * 64 + tx * 4];
#pragma unroll
            for (int i = 0; i < 8; i++)
#pragma unroll
                for (int c = 0; c < 4; c++)
                    Oa[i][c] = fmaf(pf[i], vf[c], Oa[i][c]);
        }
    }

    // Epilogue: normalize + write natural layout
#pragma unroll
    for (int i = 0; i < 8; i++) {
        const float inv = 1.f / l_i[i];
        const int q = qb + ty * 8 + i;
        float4 v = make_float4(Oa[i][0] * inv, Oa[i][1] * inv,
                               Oa[i][2] * inv, Oa[i][3] * inv);
        *(float4*)(O + ((size_t)(b * 2048 + q) << 10) + h * 64 + tx * 4) = v;
    }
}

// ---------------------------------------------------------------------------
extern "C" void kernel_launch(void* const* d_in, const int* in_sizes, int n_in,
                              void* d_out, int out_size)
{
    const float* q  = (const float*)d_in[0];
    const float* Wq = (const float*)d_in[1];
    const float* bq = (const float*)d_in[2];
    const float* Wk = (const float*)d_in[3];
    const float* bk = (const float*)d_in[4];
    const float* Wv = (const float*)d_in[5];
    const float* bv = (const float*)d_in[6];
    const float* Wo = (const float*)d_in[7];
    const float* bo = (const float*)d_in[8];

    float *Qt, *Kt, *Vb, *At;
    cudaGetSymbolAddress((void**)&Qt, g_Qt);
    cudaGetSymbolAddress((void**)&Kt, g_Kt);
    cudaGetSymbolAddress((void**)&Vb, g_V);
    cudaGetSymbolAddress((void**)&At, g_At);

    const int FLASH_SMEM = (8192 * 2 + 8192 + 16384) * 4;  // 163840 B
    cudaFuncSetAttribute(flash_attn_kernel,
                         cudaFuncAttributeMaxDynamicSharedMemorySize, FLASH_SMEM);

    dim3 gemm_grid(DD / 128, (BB * SS) / 128);   // (8, 32)

    sgemm_bias_kernel<1><<<gemm_grid, 256>>>(q, Wq, bq, Qt);
    sgemm_bias_kernel<1><<<gemm_grid, 256>>>(q, Wk, bk, Kt);
    sgemm_bias_kernel<0><<<gemm_grid, 256>>>(q, Wv, bv, Vb);

    flash_attn_kernel<<<dim3(SS / 128, HH, BB), 256, FLASH_SMEM>>>(Qt, Kt, Vb, At);

    sgemm_bias_kernel<0><<<gemm_grid, 256>>>(At, Wo, bo, (float*)d_out);
}

// round 4
// speedup vs baseline: 1.4739x; 1.4739x over previous
#include <cuda_runtime.h>
#include <cuda_bf16.h>
#include <math.h>
#include <stdint.h>

// Problem constants
#define BB   2
#define SS   2048
#define DD   1024
#define HH   16
#define HS   64
#define MM   (BB * SS)     // 4096

// ---------------------------------------------------------------------------
// Scratch (device globals: allocation-free rule)
// ---------------------------------------------------------------------------
__device__ float          g_Qt[BB * DD * SS];      // [b][h*64+d][s] fp32
__device__ float          g_Kt[BB * DD * SS];      // [b][h*64+d][s] fp32
__device__ float          g_V [BB * SS * DD];      // natural fp32
__device__ __nv_bfloat16  g_qh[MM * DD];           // q split hi
__device__ __nv_bfloat16  g_ql[MM * DD];           // q split lo
__device__ __nv_bfloat16  g_Ath[MM * DD];          // attn out split hi
__device__ __nv_bfloat16  g_Atl[MM * DD];          // attn out split lo
__device__ __nv_bfloat16  g_Wqh[DD * DD], g_Wql[DD * DD];
__device__ __nv_bfloat16  g_Wkh[DD * DD], g_Wkl[DD * DD];
__device__ __nv_bfloat16  g_Wvh[DD * DD], g_Wvl[DD * DD];
__device__ __nv_bfloat16  g_Woh[DD * DD], g_Wol[DD * DD];

// ---------------------------------------------------------------------------
// Helpers (family-portable PTX only: ldmatrix / mma.sync / cp.async)
// ---------------------------------------------------------------------------
__device__ __forceinline__ uint32_t smem_to_u32(const void* p) {
    uint32_t a;
    asm("{ .reg .u64 t; cvta.to.shared.u64 t, %1; cvt.u32.u64 %0, t; }"
        : "=r"(a) : "l"(p));
    return a;
}

__device__ __forceinline__ void ldsm4(uint32_t (&r)[4], uint32_t addr) {
    asm volatile("ldmatrix.sync.aligned.m8n8.x4.shared.b16 {%0,%1,%2,%3}, [%4];"
                 : "=r"(r[0]), "=r"(r[1]), "=r"(r[2]), "=r"(r[3]) : "r"(addr));
}

__device__ __forceinline__ void mma16816(float (&d)[4], const uint32_t (&a)[4],
                                         uint32_t b0, uint32_t b1) {
    asm volatile(
        "mma.sync.aligned.m16n8k16.row.col.f32.bf16.bf16.f32 "
        "{%0,%1,%2,%3}, {%4,%5,%6,%7}, {%8,%9}, {%0,%1,%2,%3};"
        : "+f"(d[0]), "+f"(d[1]), "+f"(d[2]), "+f"(d[3])
        : "r"(a[0]), "r"(a[1]), "r"(a[2]), "r"(a[3]), "r"(b0), "r"(b1));
}

#define CP_ASYNC16(dst, src) \
    asm volatile("cp.async.cg.shared.global [%0], [%1], 16;" :: "r"(dst), "l"(src))
#define CP_COMMIT() asm volatile("cp.async.commit_group;" ::: "memory")
#define CP_WAIT1()  asm volatile("cp.async.wait_group 1;" ::: "memory")
#define CP_WAIT0()  asm volatile("cp.async.wait_group 0;" ::: "memory")

__device__ __forceinline__ void split_bf16(float x, __nv_bfloat16& hi, __nv_bfloat16& lo) {
    hi = __float2bfloat16(x);
    lo = __float2bfloat16(x - __bfloat162float(hi));
}

// ---------------------------------------------------------------------------
// convert q (fp32) -> hi/lo bf16
// ---------------------------------------------------------------------------
__global__ void convert_split_kernel(const float* __restrict__ x,
                                     __nv_bfloat16* __restrict__ xh,
                                     __nv_bfloat16* __restrict__ xl)
{
    int i = blockIdx.x * blockDim.x + threadIdx.x;   // i indexes float4
    float4 v = ((const float4*)x)[i];
    __nv_bfloat16 h0,h1,h2,h3,l0,l1,l2,l3;
    split_bf16(v.x,h0,l0); split_bf16(v.y,h1,l1);
    split_bf16(v.z,h2,l2); split_bf16(v.w,h3,l3);
    __nv_bfloat162* ph = (__nv_bfloat162*)xh + i*2;
    __nv_bfloat162* pl = (__nv_bfloat162*)xl + i*2;
    ph[0] = __halves2bfloat162(h0,h1); ph[1] = __halves2bfloat162(h2,h3);
    pl[0] = __halves2bfloat162(l0,l1); pl[1] = __halves2bfloat162(l2,l3);
}

// ---------------------------------------------------------------------------
// weight transpose + split: W[k][n] fp32 -> Wt hi/lo bf16 [n][k]
// ---------------------------------------------------------------------------
__global__ void wconv_kernel(const float* __restrict__ W,
                             __nv_bfloat16* __restrict__ Wth,
                             __nv_bfloat16* __restrict__ Wtl)
{
    __shared__ float t[32][33];
    int k = blockIdx.y * 32 + threadIdx.y;
    int n = blockIdx.x * 32 + threadIdx.x;
    t[threadIdx.y][threadIdx.x] = W[k * DD + n];
    __syncthreads();
    int nn = blockIdx.x * 32 + threadIdx.y;
    int kk = blockIdx.y * 32 + threadIdx.x;
    float v = t[threadIdx.x][threadIdx.y];
    __nv_bfloat16 hi, lo; split_bf16(v, hi, lo);
    Wth[nn * DD + kk] = hi;
    Wtl[nn * DD + kk] = lo;
}

// ---------------------------------------------------------------------------
// bf16x3 mma.sync GEMM: C[m][n] = (Ah+Al)[m][:]·(Bh+Bl)[n][:] + bias[n]
// (Al*Bl dropped).  A [4096][1024] K-major bf16, B [1024][1024] K-major bf16.
// CTA 128x128, 8 warps (4m x 2n), warp tile 32x64, KC=64, 2-stage cp.async.
// TRANSOUT=0: C[m][n].  TRANSOUT=1: C[(b*1024+n)*2048 + s], m = b*2048+s.
// ---------------------------------------------------------------------------
#define KC        64
#define NCHUNK    (DD / KC)          // 16
#define TILE_B    16384              // 128 rows x 128 bytes
#define STG_B     (4 * TILE_B)       // 65536
#define OFF_AH    0
#define OFF_AL    TILE_B
#define OFF_BH    (2 * TILE_B)
#define OFF_BL    (3 * TILE_B)
#define GEMM_SMEM (2 * STG_B)        // 131072
#define PADC      133                // epilogue fp32 row pitch (conflict-free cols)

// SW128 swizzle of a tile-local (row, chunk16B) pair, as byte offset
__device__ __forceinline__ uint32_t swoff(int row, int c) {
    return (uint32_t)(row * 128 + ((c ^ (row & 7)) << 4));
}

template <int TRANSOUT>
__global__ __launch_bounds__(256)
void bf16x3_gemm_kernel(const __nv_bfloat16* __restrict__ Ah,
                        const __nv_bfloat16* __restrict__ Al,
                        const __nv_bfloat16* __restrict__ Bh,
                        const __nv_bfloat16* __restrict__ Bl,
                        const float* __restrict__ bias,
                        float* __restrict__ C)
{
    extern __shared__ char smem[];
    const uint32_t sb = smem_to_u32(smem);
    const int tid  = threadIdx.x;
    const int wid  = tid >> 5;
    const int lane = tid & 31;

    const int n0 = blockIdx.x * 128;
    const int m0 = blockIdx.y * 128;

    const int mw = wid & 3;          // warp m index (0..3) -> rows mw*32..
    const int nw = wid >> 2;         // warp n index (0..1) -> cols nw*64..
    const int m_base = mw * 32;
    const int n_base = nw * 64;

    // gmem bases (tile-local row r -> global row m0+r / n0+r)
    const __nv_bfloat16* gAh = Ah + (size_t)m0 * DD;
    const __nv_bfloat16* gAl = Al + (size_t)m0 * DD;
    const __nv_bfloat16* gBh = Bh + (size_t)n0 * DD;
    const __nv_bfloat16* gBl = Bl + (size_t)n0 * DD;

    // fill mapping: idx -> row = idx>>3, chunk = idx&7 (4 iters x 256 thr / tile)
    const int f_row = tid >> 3;          // rows f_row + 32*r4
    const int f_c   = tid & 7;

    float acc[2][8][4];
#pragma unroll
    for (int i = 0; i < 2; i++)
#pragma unroll
        for (int j = 0; j < 8; j++)
#pragma unroll
            for (int e = 0; e < 4; e++) acc[i][j][e] = 0.f;

    // ldmatrix per-lane row precompute
    const int lane15 = lane & 15, laneHi = lane >> 4;
    int aRow[2], bRow[4];
#pragma unroll
    for (int i = 0; i < 2; i++) aRow[i] = m_base + i * 16 + lane15;
#pragma unroll
    for (int j = 0; j < 4; j++) bRow[j] = n_base + j * 16 + lane15;

    auto fill_stage = [&](int chunk, int stg) {
        const uint32_t base = sb + (uint32_t)stg * STG_B;
        const int k0 = chunk * KC;
#pragma unroll
        for (int r4 = 0; r4 < 4; r4++) {
            const int row = f_row + r4 * 32;
            const uint32_t so = swoff(row, f_c);
            const size_t go = (size_t)row * DD + k0 + f_c * 8;
            CP_ASYNC16(base + OFF_AH + so, gAh + go);
            CP_ASYNC16(base + OFF_AL + so, gAl + go);
            CP_ASYNC16(base + OFF_BH + so, gBh + go);
            CP_ASYNC16(base + OFF_BL + so, gBl + go);
        }
    };

    fill_stage(0, 0);
    CP_COMMIT();

    for (int c = 0; c < NCHUNK; c++) {
        if (c + 1 < NCHUNK) {
            fill_stage(c + 1, (c + 1) & 1);
            CP_COMMIT();
            CP_WAIT1();
        } else {
            CP_WAIT0();
        }
        __syncthreads();

        const uint32_t base = sb + (uint32_t)(c & 1) * STG_B;
        const uint32_t bAH = base + OFF_AH, bAL = base + OFF_AL;
        const uint32_t bBH = base + OFF_BH, bBL = base + OFF_BL;

#pragma unroll
        for (int ks = 0; ks < 4; ks++) {
            const int ch = ks * 2 + laneHi;   // 16B chunk index for this lane
            uint32_t ah[2][4], al[2][4], bh[4][4], bl[4][4];
#pragma unroll
            for (int i = 0; i < 2; i++) {
                const uint32_t ro = (uint32_t)(aRow[i] * 128);
                const uint32_t co = (uint32_t)((ch ^ (aRow[i] & 7)) << 4);
                ldsm4(ah[i], bAH + ro + co);
                ldsm4(al[i], bAL + ro + co);
            }
#pragma unroll
            for (int j = 0; j < 4; j++) {
                const uint32_t ro = (uint32_t)(bRow[j] * 128);
                const uint32_t co = (uint32_t)((ch ^ (bRow[j] & 7)) << 4);
                ldsm4(bh[j], bBH + ro + co);
                ldsm4(bl[j], bBL + ro + co);
            }
#pragma unroll
            for (int i = 0; i < 2; i++)
#pragma unroll
                for (int j = 0; j < 4; j++) {
                    mma16816(acc[i][2*j],   ah[i], bh[j][0], bh[j][2]);
                    mma16816(acc[i][2*j+1], ah[i], bh[j][1], bh[j][3]);
                    mma16816(acc[i][2*j],   ah[i], bl[j][0], bl[j][2]);
                    mma16816(acc[i][2*j+1], ah[i], bl[j][1], bl[j][3]);
                    mma16816(acc[i][2*j],   al[i], bh[j][0], bh[j][2]);
                    mma16816(acc[i][2*j+1], al[i], bh[j][1], bh[j][3]);
                }
        }
        __syncthreads();   // stage reuse guard
    }

    // ---- epilogue via padded smem tile (reuses pipeline smem) ----
    float* ts = (float*)smem;                       // [128][PADC]
    float* sbias = (float*)smem + 128 * PADC;       // [128]
    if (tid < 128) sbias[tid] = bias[n0 + tid];

    const int cr = lane >> 2, cc = (lane & 3) * 2;  // C frag coords
#pragma unroll
    for (int i = 0; i < 2; i++) {
        const int r0 = m_base + i * 16 + cr;
#pragma unroll
        for (int j = 0; j < 8; j++) {
            const int cn = n_base + j * 8 + cc;
            ts[r0 * PADC + cn]           = acc[i][j][0];
            ts[r0 * PADC + cn + 1]       = acc[i][j][1];
            ts[(r0 + 8) * PADC + cn]     = acc[i][j][2];
            ts[(r0 + 8) * PADC + cn + 1] = acc[i][j][3];
        }
    }
    __syncthreads();

    if (TRANSOUT == 0) {
#pragma unroll 4
        for (int it = 0; it < 64; it++) {
            const int idx = it * 256 + tid;
            const int m = idx >> 7, n = idx & 127;
            C[(size_t)(m0 + m) * DD + n0 + n] = ts[m * PADC + n] + sbias[n];
        }
    } else {
        const int b  = m0 >> 11;
        const int s0 = m0 & 2047;
        const int sl = tid & 31;
        const int ng = tid >> 5;            // 0..7
#pragma unroll
        for (int j = 0; j < 16; j++) {
            const int n = ng + 8 * j;
            const float bv = sbias[n];
            float* Cp = C + (((size_t)(b * 1024 + n0 + n)) << 11) + s0;
#pragma unroll
            for (int i = 0; i < 4; i++) {
                const int s = sl + 32 * i;
                Cp[s] = ts[s * PADC + n] + bv;
            }
        }
    }
}

// ---------------------------------------------------------------------------
// Causal flash attention, fp32 (R1 math). Epilogue emits bf16 hi/lo for the
// O-projection.
// ---------------------------------------------------------------------------
__global__ __launch_bounds__(256, 1)
void flash_attn_kernel(const float* __restrict__ Qt,
                       const float* __restrict__ Kt,
                       const float* __restrict__ V,
                       __nv_bfloat16* __restrict__ Oh,
                       __nv_bfloat16* __restrict__ Ol)
{
    extern __shared__ float sm[];
    float* sQ = sm;                 // [d][q]  64*128
    float* sK = sm + 8192;          // [d][k]  64*128
    float* sV = sm + 16384;         // [k][d]  128*64
    float* sP = sm + 24576;         // [k][q]  128*128, swizzled

    const int tid = threadIdx.x;
    const int tx = tid & 15, ty = tid >> 4;
    const int qt = (int)gridDim.x - 1 - (int)blockIdx.x;
    const int qb = qt * 128;
    const int h  = blockIdx.y;
    const int b  = blockIdx.z;

    const float scale = 0.125f;

    const size_t headoff = ((size_t)(b * 1024 + h * 64)) << 11;
    const float* Qg = Qt + headoff + qb;
    const float* Kg = Kt + headoff;
    const float* Vg = V + ((size_t)b << 21) + h * 64;

    {
        const int d0 = tid >> 5;
        const int c4 = (tid & 31) << 2;
#pragma unroll
        for (int it = 0; it < 8; it++) {
            const int dd = it * 8 + d0;
            float4 v = *(const float4*)(Qg + ((size_t)dd << 11) + c4);
            v.x *= scale; v.y *= scale; v.z *= scale; v.w *= scale;
            *(float4*)&sQ[dd * 128 + c4] = v;
        }
    }

    float m_i[8], l_i[8], Oa[8][4];
#pragma unroll
    for (int i = 0; i < 8; i++) {
        m_i[i] = -INFINITY; l_i[i] = 0.f;
#pragma unroll
        for (int c = 0; c < 4; c++) Oa[i][c] = 0.f;
    }

    const int nkt = qt + 1;
    for (int kt2 = 0; kt2 < nkt; kt2++) {
        const int kb = kt2 * 128;
        __syncthreads();

        {
            const int d0 = tid >> 5;
            const int c4 = (tid & 31) << 2;
#pragma unroll
            for (int it = 0; it < 8; it++) {
                const int dd = it * 8 + d0;
                *(float4*)&sK[dd * 128 + c4] =
                    *(const float4*)(Kg + ((size_t)dd << 11) + kb + c4);
            }
        }
        {
#pragma unroll
            for (int it = 0; it < 8; it++) {
                const int idx = it * 256 + tid;
                const int k  = idx >> 4;
                const int d4 = (idx & 15) << 2;
                *(float4*)&sV[k * 64 + d4] =
                    *(const float4*)(Vg + ((size_t)(kb + k) << 10) + d4);
            }
        }
        __syncthreads();

        float sc[8][8];
#pragma unroll
        for (int i = 0; i < 8; i++)
#pragma unroll
            for (int j = 0; j < 8; j++) sc[i][j] = 0.f;

#pragma unroll 8
        for (int d = 0; d < 64; d++) {
            float qf[8], kf[8];
            *(float4*)&qf[0] = *(const float4*)&sQ[d * 128 + ty * 8];
            *(float4*)&qf[4] = *(const float4*)&sQ[d * 128 + ty * 8 + 4];
            *(float4*)&kf[0] = *(const float4*)&sK[d * 128 + tx * 4];
            *(float4*)&kf[4] = *(const float4*)&sK[d * 128 + 64 + tx * 4];
#pragma unroll
            for (int i = 0; i < 8; i++)
#pragma unroll
                for (int j = 0; j < 8; j++)
                    sc[i][j] = fmaf(qf[i], kf[j], sc[i][j]);
        }

        if (kt2 == qt) {
#pragma unroll
            for (int i = 0; i < 8; i++) {
                const int q = qb + ty * 8 + i;
#pragma unroll
                for (int j = 0; j < 8; j++) {
                    const int k = kb + ((j < 4) ? (tx * 4 + j) : (64 + tx * 4 + (j - 4)));
                    if (k > q) sc[i][j] = -INFINITY;
                }
            }
        }

#pragma unroll
        for (int i = 0; i < 8; i++) {
            float mx = sc[i][0];
#pragma unroll
            for (int j = 1; j < 8; j++) mx = fmaxf(mx, sc[i][j]);
            mx = fmaxf(mx, __shfl_xor_sync(0xffffffffu, mx, 1));
            mx = fmaxf(mx, __shfl_xor_sync(0xffffffffu, mx, 2));
            mx = fmaxf(mx, __shfl_xor_sync(0xffffffffu, mx, 4));
            mx = fmaxf(mx, __shfl_xor_sync(0xffffffffu, mx, 8));
            const float mn = fmaxf(m_i[i], mx);
            const float al = __expf(m_i[i] - mn);
            m_i[i] = mn;
            float rs = 0.f;
#pragma unroll
            for (int j = 0; j < 8; j++) {
                sc[i][j] = __expf(sc[i][j] - mn);
                rs += sc[i][j];
            }
            rs += __shfl_xor_sync(0xffffffffu, rs, 1);
            rs += __shfl_xor_sync(0xffffffffu, rs, 2);
            rs += __shfl_xor_sync(0xffffffffu, rs, 4);
            rs += __shfl_xor_sync(0xffffffffu, rs, 8);
            l_i[i] = l_i[i] * al + rs;
#pragma unroll
            for (int c = 0; c < 4; c++) Oa[i][c] *= al;
        }

#pragma unroll
        for (int j = 0; j < 8; j++) {
            const int krow = (j < 4) ? (tx * 4 + j) : (64 + tx * 4 + (j - 4));
            const int swz = (krow >> 2) & 7;
            float4 v0 = make_float4(sc[0][j], sc[1][j], sc[2][j], sc[3][j]);
            float4 v1 = make_float4(sc[4][j], sc[5][j], sc[6][j], sc[7][j]);
            *(float4*)&sP[krow * 128 + (((2 * ty + 0) ^ swz) << 2)] = v0;
            *(float4*)&sP[krow * 128 + (((2 * ty + 1) ^ swz) << 2)] = v1;
        }
        __syncthreads();

#pragma unroll 4
        for (int k = 0; k < 128; k++) {
            const int swz = (k >> 2) & 7;
            float pf[8], vf[4];
            *(float4*)&pf[0] = *(const float4*)&sP[k * 128 + (((2 * ty + 0) ^ swz) << 2)];
            *(float4*)&pf[4] = *(const float4*)&sP[k * 128 + (((2 * ty + 1) ^ swz) << 2)];
            *(float4*)&vf[0] = *(const float4*)&sV[k * 64 + tx * 4];
#pragma unroll
            for (int i = 0; i < 8; i++)
#pragma unroll
                for (int c = 0; c < 4; c++)
                    Oa[i][c] = fmaf(pf[i], vf[c], Oa[i][c]);
        }
    }

    // Epilogue: normalize, split to bf16 hi/lo, write natural layout
#pragma unroll
    for (int i = 0; i < 8; i++) {
        const float inv = 1.f / l_i[i];
        const int q = qb + ty * 8 + i;
        const size_t base = ((size_t)(b * 2048 + q) << 10) + h * 64 + tx * 4;
        __nv_bfloat16 hh[4], ll[4];
#pragma unroll
        for (int c = 0; c < 4; c++) split_bf16(Oa[i][c] * inv, hh[c], ll[c]);
        ((__nv_bfloat162*)(Oh + base))[0] = __halves2bfloat162(hh[0], hh[1]);
        ((__nv_bfloat162*)(Oh + base))[1] = __halves2bfloat162(hh[2], hh[3]);
        ((__nv_bfloat162*)(Ol + base))[0] = __halves2bfloat162(ll[0], ll[1]);
        ((__nv_bfloat162*)(Ol + base))[1] = __halves2bfloat162(ll[2], ll[3]);
    }
}

// ---------------------------------------------------------------------------
extern "C" void kernel_launch(void* const* d_in, const int* in_sizes, int n_in,
                              void* d_out, int out_size)
{
    const float* q  = (const float*)d_in[0];
    const float* Wq = (const float*)d_in[1];
    const float* bq = (const float*)d_in[2];
    const float* Wk = (const float*)d_in[3];
    const float* bk = (const float*)d_in[4];
    const float* Wv = (const float*)d_in[5];
    const float* bv = (const float*)d_in[6];
    const float* Wo = (const float*)d_in[7];
    const float* bo = (const float*)d_in[8];

    float *Qt, *Kt, *Vb;
    __nv_bfloat16 *qh, *ql, *Ath, *Atl;
    __nv_bfloat16 *Wqh, *Wql, *Wkh, *Wkl, *Wvh, *Wvl, *Woh, *Wol;
    cudaGetSymbolAddress((void**)&Qt,  g_Qt);
    cudaGetSymbolAddress((void**)&Kt,  g_Kt);
    cudaGetSymbolAddress((void**)&Vb,  g_V);
    cudaGetSymbolAddress((void**)&qh,  g_qh);
    cudaGetSymbolAddress((void**)&ql,  g_ql);
    cudaGetSymbolAddress((void**)&Ath, g_Ath);
    cudaGetSymbolAddress((void**)&Atl, g_Atl);
    cudaGetSymbolAddress((void**)&Wqh, g_Wqh);
    cudaGetSymbolAddress((void**)&Wql, g_Wql);
    cudaGetSymbolAddress((void**)&Wkh, g_Wkh);
    cudaGetSymbolAddress((void**)&Wkl, g_Wkl);
    cudaGetSymbolAddress((void**)&Wvh, g_Wvh);
    cudaGetSymbolAddress((void**)&Wvl, g_Wvl);
    cudaGetSymbolAddress((void**)&Woh, g_Woh);
    cudaGetSymbolAddress((void**)&Wol, g_Wol);

    const int FLASH_SMEM = (8192 * 2 + 8192 + 16384) * 4;  // 163840 B
    cudaFuncSetAttribute(flash_attn_kernel,
                         cudaFuncAttributeMaxDynamicSharedMemorySize, FLASH_SMEM);
    cudaFuncSetAttribute(bf16x3_gemm_kernel<0>,
                         cudaFuncAttributeMaxDynamicSharedMemorySize, GEMM_SMEM);
    cudaFuncSetAttribute(bf16x3_gemm_kernel<1>,
                         cudaFuncAttributeMaxDynamicSharedMemorySize, GEMM_SMEM);

    // 1. input + weight conversions
    convert_split_kernel<<<4096, 256>>>(q, qh, ql);
    dim3 wgrid(32, 32), wblk(32, 32);
    wconv_kernel<<<wgrid, wblk>>>(Wq, Wqh, Wql);
    wconv_kernel<<<wgrid, wblk>>>(Wk, Wkh, Wkl);
    wconv_kernel<<<wgrid, wblk>>>(Wv, Wvh, Wvl);
    wconv_kernel<<<wgrid, wblk>>>(Wo, Woh, Wol);

    // 2. projections on tensor cores (mma.sync bf16x3)
    dim3 ggrid(DD / 128, MM / 128);   // (8, 32)
    bf16x3_gemm_kernel<1><<<ggrid, 256, GEMM_SMEM>>>(qh, ql, Wqh, Wql, bq, Qt);
    bf16x3_gemm_kernel<1><<<ggrid, 256, GEMM_SMEM>>>(qh, ql, Wkh, Wkl, bk, Kt);
    bf16x3_gemm_kernel<0><<<ggrid, 256, GEMM_SMEM>>>(qh, ql, Wvh, Wvl, bv, Vb);

    // 3. attention
    flash_attn_kernel<<<dim3(SS / 128, HH, BB), 256, FLASH_SMEM>>>(Qt, Kt, Vb, Ath, Atl);

    // 4. output projection
    bf16x3_gemm_kernel<0><<<ggrid, 256, GEMM_SMEM>>>(Ath, Atl, Woh, Wol, bo, (float*)d_out);
}

// round 6
// speedup vs baseline: 2.4162x; 1.6393x over previous
#include <cuda_runtime.h>
#include <cuda_bf16.h>
#include <math.h>
#include <stdint.h>

// Problem constants
#define BB   2
#define SS   2048
#define DD   1024
#define HH   16
#define HS   64
#define MM   (BB * SS)     // 4096

// ---------------------------------------------------------------------------
// Scratch (device globals: allocation-free rule)
// ---------------------------------------------------------------------------
__device__ __nv_bfloat16  g_qh[MM * DD], g_ql[MM * DD];     // input q split
__device__ __nv_bfloat16  g_Qph[MM * DD], g_Qpl[MM * DD];   // projected Q split
__device__ __nv_bfloat16  g_Kph[MM * DD], g_Kpl[MM * DD];   // projected K split
__device__ __nv_bfloat16  g_Vph[MM * DD], g_Vpl[MM * DD];   // projected V split
__device__ __nv_bfloat16  g_Ath[MM * DD], g_Atl[MM * DD];   // attention out split
__device__ __nv_bfloat16  g_Wqh[DD * DD], g_Wql[DD * DD];
__device__ __nv_bfloat16  g_Wkh[DD * DD], g_Wkl[DD * DD];
__device__ __nv_bfloat16  g_Wvh[DD * DD], g_Wvl[DD * DD];
__device__ __nv_bfloat16  g_Woh[DD * DD], g_Wol[DD * DD];

// ---------------------------------------------------------------------------
// Helpers (family-portable PTX only: ldmatrix / mma.sync / cp.async)
// ---------------------------------------------------------------------------
__device__ __forceinline__ uint32_t smem_to_u32(const void* p) {
    uint32_t a;
    asm("{ .reg .u64 t; cvta.to.shared.u64 t, %1; cvt.u32.u64 %0, t; }"
        : "=r"(a) : "l"(p));
    return a;
}
__device__ __forceinline__ void ldsm4(uint32_t (&r)[4], uint32_t addr) {
    asm volatile("ldmatrix.sync.aligned.m8n8.x4.shared.b16 {%0,%1,%2,%3}, [%4];"
                 : "=r"(r[0]), "=r"(r[1]), "=r"(r[2]), "=r"(r[3]) : "r"(addr));
}
__device__ __forceinline__ void ldsm4t(uint32_t (&r)[4], uint32_t addr) {
    asm volatile("ldmatrix.sync.aligned.m8n8.x4.trans.shared.b16 {%0,%1,%2,%3}, [%4];"
                 : "=r"(r[0]), "=r"(r[1]), "=r"(r[2]), "=r"(r[3]) : "r"(addr));
}
__device__ __forceinline__ void mma16816(float (&d)[4], const uint32_t (&a)[4],
                                         uint32_t b0, uint32_t b1) {
    asm volatile(
        "mma.sync.aligned.m16n8k16.row.col.f32.bf16.bf16.f32 "
        "{%0,%1,%2,%3}, {%4,%5,%6,%7}, {%8,%9}, {%0,%1,%2,%3};"
        : "+f"(d[0]), "+f"(d[1]), "+f"(d[2]), "+f"(d[3])
        : "r"(a[0]), "r"(a[1]), "r"(a[2]), "r"(a[3]), "r"(b0), "r"(b1));
}
#define CP_ASYNC16(dst, src) \
    asm volatile("cp.async.cg.shared.global [%0], [%1], 16;" :: "r"(dst), "l"(src))
#define CP_COMMIT() asm volatile("cp.async.commit_group;" ::: "memory")
#define CP_WAIT1()  asm volatile("cp.async.wait_group 1;" ::: "memory")
#define CP_WAIT0()  asm volatile("cp.async.wait_group 0;" ::: "memory")

__device__ __forceinline__ float fexp2(float x) {
    float r;
    asm("ex2.approx.f32 %0, %1;" : "=f"(r) : "f"(x));
    return r;
}
__device__ __forceinline__ void split_bf16(float x, __nv_bfloat16& hi, __nv_bfloat16& lo) {
    hi = __float2bfloat16(x);
    lo = __float2bfloat16(x - __bfloat162float(hi));
}
// pack (x,y) -> bf162 hi + residual bf162 lo (as u32)
__device__ __forceinline__ void split2(float x, float y, uint32_t& hi, uint32_t& lo) {
    __nv_bfloat162 h = __floats2bfloat162_rn(x, y);
    float hx = __low2float(h), hy = __high2float(h);
    __nv_bfloat162 l = __floats2bfloat162_rn(x - hx, y - hy);
    hi = *(uint32_t*)&h;  lo = *(uint32_t*)&l;
}

// SW128 swizzle of (row, 16B-chunk) -> byte offset (128B rows)
__device__ __forceinline__ uint32_t swoff(int row, int c) {
    return (uint32_t)(row * 128 + ((c ^ (row & 7)) << 4));
}

// ---------------------------------------------------------------------------
// convert q (fp32) -> hi/lo bf16
// ---------------------------------------------------------------------------
__global__ void convert_split_kernel(const float* __restrict__ x,
                                     __nv_bfloat16* __restrict__ xh,
                                     __nv_bfloat16* __restrict__ xl)
{
    int i = blockIdx.x * blockDim.x + threadIdx.x;   // i indexes float4
    float4 v = ((const float4*)x)[i];
    uint32_t h0, l0, h1, l1;
    split2(v.x, v.y, h0, l0);
    split2(v.z, v.w, h1, l1);
    uint32_t* ph = (uint32_t*)xh + i * 2;
    uint32_t* pl = (uint32_t*)xl + i * 2;
    ph[0] = h0; ph[1] = h1;
    pl[0] = l0; pl[1] = l1;
}

// ---------------------------------------------------------------------------
// weight transpose + split: W[k][n] fp32 -> Wt hi/lo bf16 [n][k]
// ---------------------------------------------------------------------------
__global__ void wconv_kernel(const float* __restrict__ W,
                             __nv_bfloat16* __restrict__ Wth,
                             __nv_bfloat16* __restrict__ Wtl)
{
    __shared__ float t[32][33];
    int k = blockIdx.y * 32 + threadIdx.y;
    int n = blockIdx.x * 32 + threadIdx.x;
    t[threadIdx.y][threadIdx.x] = W[k * DD + n];
    __syncthreads();
    int nn = blockIdx.x * 32 + threadIdx.y;
    int kk = blockIdx.y * 32 + threadIdx.x;
    float v = t[threadIdx.x][threadIdx.y];
    __nv_bfloat16 hi, lo; split_bf16(v, hi, lo);
    Wth[nn * DD + kk] = hi;
    Wtl[nn * DD + kk] = lo;
}

// ---------------------------------------------------------------------------
// bf16x3 mma.sync GEMM: C = (Ah+Al)·(Bh+Bl)^T + bias (Al*Bl dropped).
// CTA 128x128, 8 warps (4m x 2n), warp 32x64, KC=64, 2-stage cp.async.
// OUTBF=0: fp32 C[m][n].  OUTBF=1: bf16 split Ch/Cl [m][n].
// ---------------------------------------------------------------------------
#define KC        64
#define NCHUNK    (DD / KC)          // 16
#define TILE_B    16384              // 128 rows x 128 bytes
#define STG_B     (4 * TILE_B)       // 65536
#define OFF_AH    0
#define OFF_AL    TILE_B
#define OFF_BH    (2 * TILE_B)
#define OFF_BL    (3 * TILE_B)
#define GEMM_SMEM (2 * STG_B)        // 131072
#define PADC      133

template <int OUTBF>
__global__ __launch_bounds__(256)
void bf16x3_gemm_kernel(const __nv_bfloat16* __restrict__ Ah,
                        const __nv_bfloat16* __restrict__ Al,
                        const __nv_bfloat16* __restrict__ Bh,
                        const __nv_bfloat16* __restrict__ Bl,
                        const float* __restrict__ bias,
                        float* __restrict__ C,
                        __nv_bfloat16* __restrict__ Ch,
                        __nv_bfloat16* __restrict__ Cl)
{
    extern __shared__ char smem[];
    const uint32_t sb = smem_to_u32(smem);
    const int tid  = threadIdx.x;
    const int wid  = tid >> 5;
    const int lane = tid & 31;

    const int n0 = blockIdx.x * 128;
    const int m0 = blockIdx.y * 128;

    const int m_base = (wid & 3) * 32;
    const int n_base = (wid >> 2) * 64;

    const __nv_bfloat16* gAh = Ah + (size_t)m0 * DD;
    const __nv_bfloat16* gAl = Al + (size_t)m0 * DD;
    const __nv_bfloat16* gBh = Bh + (size_t)n0 * DD;
    const __nv_bfloat16* gBl = Bl + (size_t)n0 * DD;

    const int f_row = tid >> 3;
    const int f_c   = tid & 7;

    float acc[2][8][4];
#pragma unroll
    for (int i = 0; i < 2; i++)
#pragma unroll
        for (int j = 0; j < 8; j++)
#pragma unroll
            for (int e = 0; e < 4; e++) acc[i][j][e] = 0.f;

    const int lane15 = lane & 15, laneHi = lane >> 4;
    int aRow[2], bRow[4];
#pragma unroll
    for (int i = 0; i < 2; i++) aRow[i] = m_base + i * 16 + lane15;
#pragma unroll
    for (int j = 0; j < 4; j++) bRow[j] = n_base + j * 16 + lane15;

    auto fill_stage = [&](int chunk, int stg) {
        const uint32_t base = sb + (uint32_t)stg * STG_B;
        const int k0 = chunk * KC;
#pragma unroll
        for (int r4 = 0; r4 < 4; r4++) {
            const int row = f_row + r4 * 32;
            const uint32_t so = swoff(row, f_c);
            const size_t go = (size_t)row * DD + k0 + f_c * 8;
            CP_ASYNC16(base + OFF_AH + so, gAh + go);
            CP_ASYNC16(base + OFF_AL + so, gAl + go);
            CP_ASYNC16(base + OFF_BH + so, gBh + go);
            CP_ASYNC16(base + OFF_BL + so, gBl + go);
        }
    };

    fill_stage(0, 0);
    CP_COMMIT();

    for (int c = 0; c < NCHUNK; c++) {
        if (c + 1 < NCHUNK) {
            fill_stage(c + 1, (c + 1) & 1);
            CP_COMMIT();
            CP_WAIT1();
        } else {
            CP_WAIT0();
        }
        __syncthreads();

        const uint32_t base = sb + (uint32_t)(c & 1) * STG_B;
        const uint32_t bAH = base + OFF_AH, bAL = base + OFF_AL;
        const uint32_t bBH = base + OFF_BH, bBL = base + OFF_BL;

#pragma unroll
        for (int ks = 0; ks < 4; ks++) {
            const int ch = ks * 2 + laneHi;
            uint32_t ah[2][4], al[2][4], bh[4][4], bl[4][4];
#pragma unroll
            for (int i = 0; i < 2; i++) {
                const uint32_t ro = (uint32_t)(aRow[i] * 128);
                const uint32_t co = (uint32_t)((ch ^ (aRow[i] & 7)) << 4);
                ldsm4(ah[i], bAH + ro + co);
                ldsm4(al[i], bAL + ro + co);
            }
#pragma unroll
            for (int j = 0; j < 4; j++) {
                const uint32_t ro = (uint32_t)(bRow[j] * 128);
                const uint32_t co = (uint32_t)((ch ^ (bRow[j] & 7)) << 4);
                ldsm4(bh[j], bBH + ro + co);
                ldsm4(bl[j], bBL + ro + co);
            }
#pragma unroll
            for (int i = 0; i < 2; i++)
#pragma unroll
                for (int j = 0; j < 4; j++) {
                    mma16816(acc[i][2*j],   ah[i], bh[j][0], bh[j][2]);
                    mma16816(acc[i][2*j+1], ah[i], bh[j][1], bh[j][3]);
                    mma16816(acc[i][2*j],   ah[i], bl[j][0], bl[j][2]);
                    mma16816(acc[i][2*j+1], ah[i], bl[j][1], bl[j][3]);
                    mma16816(acc[i][2*j],   al[i], bh[j][0], bh[j][2]);
                    mma16816(acc[i][2*j+1], al[i], bh[j][1], bh[j][3]);
                }
        }
        __syncthreads();
    }

    // ---- epilogue via padded smem tile ----
    float* ts = (float*)smem;
    float* sbias = (float*)smem + 128 * PADC;
    if (tid < 128) sbias[tid] = bias[n0 + tid];

    const int cr = lane >> 2, cc = (lane & 3) * 2;
#pragma unroll
    for (int i = 0; i < 2; i++) {
        const int r0 = m_base + i * 16 + cr;
#pragma unroll
        for (int j = 0; j < 8; j++) {
            const int cn = n_base + j * 8 + cc;
            ts[r0 * PADC + cn]           = acc[i][j][0];
            ts[r0 * PADC + cn + 1]       = acc[i][j][1];
            ts[(r0 + 8) * PADC + cn]     = acc[i][j][2];
            ts[(r0 + 8) * PADC + cn + 1] = acc[i][j][3];
        }
    }
    __syncthreads();

    if (OUTBF == 0) {
#pragma unroll 4
        for (int it = 0; it < 64; it++) {
            const int idx = it * 256 + tid;
            const int m = idx >> 7, n = idx & 127;
            C[(size_t)(m0 + m) * DD + n0 + n] = ts[m * PADC + n] + sbias[n];
        }
    } else {
#pragma unroll 4
        for (int it = 0; it < 32; it++) {
            const int idx = it * 256 + tid;
            const int m = idx >> 6, n = (idx & 63) * 2;
            float x = ts[m * PADC + n]     + sbias[n];
            float y = ts[m * PADC + n + 1] + sbias[n + 1];
            uint32_t hi, lo;
            split2(x, y, hi, lo);
            const size_t o = (size_t)(m0 + m) * DD + n0 + n;
            *(uint32_t*)(Ch + o) = hi;
            *(uint32_t*)(Cl + o) = lo;
        }
    }
}

// ---------------------------------------------------------------------------
// Causal flash attention on mma.sync, bf16x3 precision everywhere.
// BQ=BKV=128, HS=64, 256 threads (8 warps x m16). Q frags register-resident.
// smem: Qh/Ql 16KB each + 2 KV stages x (Kh,Kl,Vh,Vl 16KB each) = 160 KB.
// ---------------------------------------------------------------------------
#define FQH   0
#define FQL   16384
#define FKH   0
#define FKL   16384
#define FVH   32768
#define FVL   49152
#define FSTG(s) (32768 + (s) * 65536)
#define FLASH_SMEM 163840
#define SCL   0.18033688011112042f   /* 0.125 * log2(e) */

__global__ __launch_bounds__(256)
void flash_mma_kernel(const __nv_bfloat16* __restrict__ Qh_,
                      const __nv_bfloat16* __restrict__ Ql_,
                      const __nv_bfloat16* __restrict__ Kh_,
                      const __nv_bfloat16* __restrict__ Kl_,
                      const __nv_bfloat16* __restrict__ Vh_,
                      const __nv_bfloat16* __restrict__ Vl_,
                      __nv_bfloat16* __restrict__ Oh,
                      __nv_bfloat16* __restrict__ Ol)
{
    extern __shared__ char smem[];
    const uint32_t sb = smem_to_u32(smem);
    const int tid  = threadIdx.x;
    const int wid  = tid >> 5;
    const int lane = tid & 31;
    const int lane15 = lane & 15, laneHi = lane >> 4;
    const int cr = lane >> 2, cc = (lane & 3) * 2;

    const int qt = (int)gridDim.x - 1 - (int)blockIdx.x;   // heavy-first
    const int qb = qt * 128;
    const int h  = blockIdx.y;
    const int b  = blockIdx.z;

    const size_t hoff = (size_t)h * HS;
    const __nv_bfloat16* gQh = Qh_ + (size_t)(b * SS + qb) * DD + hoff;
    const __nv_bfloat16* gQl = Ql_ + (size_t)(b * SS + qb) * DD + hoff;
    const __nv_bfloat16* gKh = Kh_ + (size_t)(b * SS) * DD + hoff;
    const __nv_bfloat16* gKl = Kl_ + (size_t)(b * SS) * DD + hoff;
    const __nv_bfloat16* gVh = Vh_ + (size_t)(b * SS) * DD + hoff;
    const __nv_bfloat16* gVl = Vl_ + (size_t)(b * SS) * DD + hoff;

    const int f_row = tid >> 3;     // 0..31
    const int f_c   = tid & 7;

    // fill Q (once)
#pragma unroll
    for (int r4 = 0; r4 < 4; r4++) {
        const int row = f_row + r4 * 32;
        const uint32_t so = swoff(row, f_c);
        const size_t go = (size_t)row * DD + f_c * 8;
        CP_ASYNC16(sb + FQH + so, gQh + go);
        CP_ASYNC16(sb + FQL + so, gQl + go);
    }
    auto fill_kv = [&](int kb, int st) {
        const uint32_t base = sb + FSTG(st);
#pragma unroll
        for (int r4 = 0; r4 < 4; r4++) {
            const int row = f_row + r4 * 32;
            const uint32_t so = swoff(row, f_c);
            const size_t go = (size_t)(kb + row) * DD + f_c * 8;
            CP_ASYNC16(base + FKH + so, gKh + go);
            CP_ASYNC16(base + FKL + so, gKl + go);
            CP_ASYNC16(base + FVH + so, gVh + go);
            CP_ASYNC16(base + FVL + so, gVl + go);
        }
    };
    fill_kv(0, 0);
    CP_COMMIT();

    uint32_t qfh[4][4], qfl[4][4];
    float o[8][4];
#pragma unroll
    for (int j = 0; j < 8; j++)
#pragma unroll
        for (int e = 0; e < 4; e++) o[j][e] = 0.f;
    float m0 = -INFINITY, m1 = -INFINITY, l0 = 0.f, l1 = 0.f;

    // V ldsm row (per lane, fixed across loop)
    const int vrow_lane = (lane & 7) + 8 * ((lane >> 3) & 1);
    const int vchunk_hi = lane >> 4;     // +0/+1 chunk

    for (int c = 0; c <= qt; c++) {
        if (c < qt) {
            fill_kv((c + 1) * 128, (c + 1) & 1);
            CP_COMMIT();
            CP_WAIT1();
        } else {
            CP_WAIT0();
        }
        __syncthreads();

        if (c == 0) {
            // Q fragments: row-major A frags, register resident
            const int qr = wid * 16 + lane15;
            const uint32_t ro = (uint32_t)(qr * 128);
            const int sw = qr & 7;
#pragma unroll
            for (int ks = 0; ks < 4; ks++) {
                const int ch = ks * 2 + laneHi;
                const uint32_t co = (uint32_t)((ch ^ sw) << 4);
                ldsm4(qfh[ks], sb + FQH + ro + co);
                ldsm4(qfl[ks], sb + FQL + ro + co);
            }
        }

        const uint32_t base = sb + FSTG(c & 1);

        // ---- scores ----
        float acc[16][4];
#pragma unroll
        for (int j = 0; j < 16; j++)
#pragma unroll
            for (int e = 0; e < 4; e++) acc[j][e] = 0.f;

#pragma unroll
        for (int ks = 0; ks < 4; ks++) {
            const int ch = ks * 2 + laneHi;
#pragma unroll
            for (int j = 0; j < 8; j++) {
                const int br = j * 16 + lane15;
                const uint32_t off = (uint32_t)(br * 128 + ((ch ^ (br & 7)) << 4));
                uint32_t kh[4], kl[4];
                ldsm4(kh, base + FKH + off);
                ldsm4(kl, base + FKL + off);
                mma16816(acc[2*j],   qfh[ks], kh[0], kh[2]);
                mma16816(acc[2*j+1], qfh[ks], kh[1], kh[3]);
                mma16816(acc[2*j],   qfh[ks], kl[0], kl[2]);
                mma16816(acc[2*j+1], qfh[ks], kl[1], kl[3]);
                mma16816(acc[2*j],   qfl[ks], kh[0], kh[2]);
                mma16816(acc[2*j+1], qfl[ks], kh[1], kh[3]);
            }
        }

        // ---- causal mask (diagonal tile) ----
        if (c == qt) {
            const int qr0 = wid * 16 + cr;
#pragma unroll
            for (int j = 0; j < 16; j++) {
                const int col = j * 8 + cc;
                if (col     > qr0)     acc[j][0] = -INFINITY;
                if (col + 1 > qr0)     acc[j][1] = -INFINITY;
                if (col     > qr0 + 8) acc[j][2] = -INFINITY;
                if (col + 1 > qr0 + 8) acc[j][3] = -INFINITY;
            }
        }

        // ---- online softmax (fp32, scale folded into exp2) ----
        float mx0 = -INFINITY, mx1 = -INFINITY;
#pragma unroll
        for (int j = 0; j < 16; j++) {
            mx0 = fmaxf(mx0, fmaxf(acc[j][0], acc[j][1]));
            mx1 = fmaxf(mx1, fmaxf(acc[j][2], acc[j][3]));
        }
        mx0 = fmaxf(mx0, __shfl_xor_sync(0xffffffffu, mx0, 1));
        mx0 = fmaxf(mx0, __shfl_xor_sync(0xffffffffu, mx0, 2));
        mx1 = fmaxf(mx1, __shfl_xor_sync(0xffffffffu, mx1, 1));
        mx1 = fmaxf(mx1, __shfl_xor_sync(0xffffffffu, mx1, 2));
        const float mn0 = fmaxf(m0, mx0);
        const float mn1 = fmaxf(m1, mx1);
        const float a0 = fexp2((m0 - mn0) * SCL);
        const float a1 = fexp2((m1 - mn1) * SCL);
        m0 = mn0; m1 = mn1;
        float rs0 = 0.f, rs1 = 0.f;
#pragma unroll
        for (int j = 0; j < 16; j++) {
            acc[j][0] = fexp2((acc[j][0] - mn0) * SCL);
            acc[j][1] = fexp2((acc[j][1] - mn0) * SCL);
            acc[j][2] = fexp2((acc[j][2] - mn1) * SCL);
            acc[j][3] = fexp2((acc[j][3] - mn1) * SCL);
            rs0 += acc[j][0] + acc[j][1];
            rs1 += acc[j][2] + acc[j][3];
        }
        rs0 += __shfl_xor_sync(0xffffffffu, rs0, 1);
        rs0 += __shfl_xor_sync(0xffffffffu, rs0, 2);
        rs1 += __shfl_xor_sync(0xffffffffu, rs1, 1);
        rs1 += __shfl_xor_sync(0xffffffffu, rs1, 2);
        l0 = l0 * a0 + rs0;
        l1 = l1 * a1 + rs1;
#pragma unroll
        for (int j = 0; j < 8; j++) {
            o[j][0] *= a0; o[j][1] *= a0;
            o[j][2] *= a1; o[j][3] *= a1;
        }

        // ---- PV: P frags straight from score regs (A-layout match) ----
#pragma unroll
        for (int t = 0; t < 8; t++) {
            uint32_t Ap[4], Alo[4];
            split2(acc[2*t][0],   acc[2*t][1],   Ap[0], Alo[0]);
            split2(acc[2*t][2],   acc[2*t][3],   Ap[1], Alo[1]);
            split2(acc[2*t+1][0], acc[2*t+1][1], Ap[2], Alo[2]);
            split2(acc[2*t+1][2], acc[2*t+1][3], Ap[3], Alo[3]);
            const int vr = t * 16 + vrow_lane;
            const uint32_t tro = (uint32_t)(vr * 128);
            const int tsw = vr & 7;
#pragma unroll
            for (int nt = 0; nt < 4; nt++) {
                const int chv = nt * 2 + vchunk_hi;
                const uint32_t voff = tro + (uint32_t)((chv ^ tsw) << 4);
                uint32_t vh[4], vl[4];
                ldsm4t(vh, base + FVH + voff);
                ldsm4t(vl, base + FVL + voff);
                mma16816(o[2*nt],   Ap,  vh[0], vh[1]);
                mma16816(o[2*nt+1], Ap,  vh[2], vh[3]);
                mma16816(o[2*nt],   Ap,  vl[0], vl[1]);
                mma16816(o[2*nt+1], Ap,  vl[2], vl[3]);
                mma16816(o[2*nt],   Alo, vh[0], vh[1]);
                mma16816(o[2*nt+1], Alo, vh[2], vh[3]);
            }
        }
        __syncthreads();
    }

    // ---- epilogue: normalize + split bf16 hi/lo, natural layout ----
    const float inv0 = 1.f / l0;
    const float inv1 = 1.f / l1;
    const int q0 = qb + wid * 16 + cr;
    const size_t r0o = (size_t)(b * SS + q0) * DD + (size_t)h * HS;
    const size_t r1o = r0o + (size_t)8 * DD;
#pragma unroll
    for (int j = 0; j < 8; j++) {
        const int d = j * 8 + cc;
        uint32_t hi, lo;
        split2(o[j][0] * inv0, o[j][1] * inv0, hi, lo);
        *(uint32_t*)(Oh + r0o + d) = hi;
        *(uint32_t*)(Ol + r0o + d) = lo;
        split2(o[j][2] * inv1, o[j][3] * inv1, hi, lo);
        *(uint32_t*)(Oh + r1o + d) = hi;
        *(uint32_t*)(Ol + r1o + d) = lo;
    }
}

// ---------------------------------------------------------------------------
extern "C" void kernel_launch(void* const* d_in, const int* in_sizes, int n_in,
                              void* d_out, int out_size)
{
    const float* q  = (const float*)d_in[0];
    const float* Wq = (const float*)d_in[1];
    const float* bq = (const float*)d_in[2];
    const float* Wk = (const float*)d_in[3];
    const float* bk = (const float*)d_in[4];
    const float* Wv = (const float*)d_in[5];
    const float* bv = (const float*)d_in[6];
    const float* Wo = (const float*)d_in[7];
    const float* bo = (const float*)d_in[8];

    __nv_bfloat16 *qh, *ql, *Qph, *Qpl, *Kph, *Kpl, *Vph, *Vpl, *Ath, *Atl;
    __nv_bfloat16 *Wqh, *Wql, *Wkh, *Wkl, *Wvh, *Wvl, *Woh, *Wol;
    cudaGetSymbolAddress((void**)&qh,  g_qh);
    cudaGetSymbolAddress((void**)&ql,  g_ql);
    cudaGetSymbolAddress((void**)&Qph, g_Qph);
    cudaGetSymbolAddress((void**)&Qpl, g_Qpl);
    cudaGetSymbolAddress((void**)&Kph, g_Kph);
    cudaGetSymbolAddress((void**)&Kpl, g_Kpl);
    cudaGetSymbolAddress((void**)&Vph, g_Vph);
    cudaGetSymbolAddress((void**)&Vpl, g_Vpl);
    cudaGetSymbolAddress((void**)&Ath, g_Ath);
    cudaGetSymbolAddress((void**)&Atl, g_Atl);
    cudaGetSymbolAddress((void**)&Wqh, g_Wqh);
    cudaGetSymbolAddress((void**)&Wql, g_Wql);
    cudaGetSymbolAddress((void**)&Wkh, g_Wkh);
    cudaGetSymbolAddress((void**)&Wkl, g_Wkl);
    cudaGetSymbolAddress((void**)&Wvh, g_Wvh);
    cudaGetSymbolAddress((void**)&Wvl, g_Wvl);
    cudaGetSymbolAddress((void**)&Woh, g_Woh);
    cudaGetSymbolAddress((void**)&Wol, g_Wol);

    cudaFuncSetAttribute(flash_mma_kernel,
                         cudaFuncAttributeMaxDynamicSharedMemorySize, FLASH_SMEM);
    cudaFuncSetAttribute(bf16x3_gemm_kernel<0>,
                         cudaFuncAttributeMaxDynamicSharedMemorySize, GEMM_SMEM);
    cudaFuncSetAttribute(bf16x3_gemm_kernel<1>,
                         cudaFuncAttributeMaxDynamicSharedMemorySize, GEMM_SMEM);

    // 1. input + weight conversions
    convert_split_kernel<<<4096, 256>>>(q, qh, ql);
    dim3 wgrid(32, 32), wblk(32, 32);
    wconv_kernel<<<wgrid, wblk>>>(Wq, Wqh, Wql);
    wconv_kernel<<<wgrid, wblk>>>(Wk, Wkh, Wkl);
    wconv_kernel<<<wgrid, wblk>>>(Wv, Wvh, Wvl);
    wconv_kernel<<<wgrid, wblk>>>(Wo, Woh, Wol);

    // 2. projections (bf16 split outputs, natural layout)
    dim3 ggrid(DD / 128, MM / 128);   // (8, 32)
    bf16x3_gemm_kernel<1><<<ggrid, 256, GEMM_SMEM>>>(qh, ql, Wqh, Wql, bq,
                                                     nullptr, Qph, Qpl);
    bf16x3_gemm_kernel<1><<<ggrid, 256, GEMM_SMEM>>>(qh, ql, Wkh, Wkl, bk,
                                                     nullptr, Kph, Kpl);
    bf16x3_gemm_kernel<1><<<ggrid, 256, GEMM_SMEM>>>(qh, ql, Wvh, Wvl, bv,
                                                     nullptr, Vph, Vpl);

    // 3. attention (mma.sync)
    flash_mma_kernel<<<dim3(SS / 128, HH, BB), 256, FLASH_SMEM>>>(
        Qph, Qpl, Kph, Kpl, Vph, Vpl, Ath, Atl);

    // 4. output projection (fp32 out)
    bf16x3_gemm_kernel<0><<<ggrid, 256, GEMM_SMEM>>>(Ath, Atl, Woh, Wol, bo,
                                                     (float*)d_out, nullptr, nullptr);
}

// round 7
// speedup vs baseline: 3.3311x; 1.3787x over previous
#include <cuda_runtime.h>
#include <cuda_fp16.h>
#include <math.h>
#include <stdint.h>

// Problem constants
#define BB   2
#define SS   2048
#define DD   1024
#define HH   16
#define HS   64
#define MM   (BB * SS)     // 4096

// ---------------------------------------------------------------------------
// Scratch (device globals: allocation-free rule)
// ---------------------------------------------------------------------------
__device__ __half  g_qh[MM * DD], g_ql[MM * DD];     // input q split (pair)
__device__ __half  g_Qph[MM * DD], g_Qpl[MM * DD];   // projected Q (pair)
__device__ __half  g_Kh[MM * DD];                    // projected K (single)
__device__ __half  g_Vh[MM * DD];                    // projected V (single)
__device__ __half  g_Ath[MM * DD], g_Atl[MM * DD];   // attention out (pair)
__device__ __half  g_Wq[DD * DD], g_Wk[DD * DD];     // transposed W (single)
__device__ __half  g_Wv[DD * DD], g_Wo[DD * DD];

// ---------------------------------------------------------------------------
// Helpers (family-portable PTX only: ldmatrix / mma.sync / cp.async)
// ---------------------------------------------------------------------------
__device__ __forceinline__ uint32_t smem_to_u32(const void* p) {
    uint32_t a;
    asm("{ .reg .u64 t; cvta.to.shared.u64 t, %1; cvt.u32.u64 %0, t; }"
        : "=r"(a) : "l"(p));
    return a;
}
__device__ __forceinline__ void ldsm4(uint32_t (&r)[4], uint32_t addr) {
    asm volatile("ldmatrix.sync.aligned.m8n8.x4.shared.b16 {%0,%1,%2,%3}, [%4];"
                 : "=r"(r[0]), "=r"(r[1]), "=r"(r[2]), "=r"(r[3]) : "r"(addr));
}
__device__ __forceinline__ void ldsm4t(uint32_t (&r)[4], uint32_t addr) {
    asm volatile("ldmatrix.sync.aligned.m8n8.x4.trans.shared.b16 {%0,%1,%2,%3}, [%4];"
                 : "=r"(r[0]), "=r"(r[1]), "=r"(r[2]), "=r"(r[3]) : "r"(addr));
}
__device__ __forceinline__ void mma16816(float (&d)[4], const uint32_t (&a)[4],
                                         uint32_t b0, uint32_t b1) {
    asm volatile(
        "mma.sync.aligned.m16n8k16.row.col.f32.f16.f16.f32 "
        "{%0,%1,%2,%3}, {%4,%5,%6,%7}, {%8,%9}, {%0,%1,%2,%3};"
        : "+f"(d[0]), "+f"(d[1]), "+f"(d[2]), "+f"(d[3])
        : "r"(a[0]), "r"(a[1]), "r"(a[2]), "r"(a[3]), "r"(b0), "r"(b1));
}
#define CP_ASYNC16(dst, src) \
    asm volatile("cp.async.cg.shared.global [%0], [%1], 16;" :: "r"(dst), "l"(src))
#define CP_COMMIT() asm volatile("cp.async.commit_group;" ::: "memory")
#define CP_WAIT1()  asm volatile("cp.async.wait_group 1;" ::: "memory")
#define CP_WAIT0()  asm volatile("cp.async.wait_group 0;" ::: "memory")

__device__ __forceinline__ float fexp2(float x) {
    float r;
    asm("ex2.approx.f32 %0, %1;" : "=f"(r) : "f"(x));
    return r;
}
// pack (x,y) -> half2 hi + residual half2 lo (as u32)
__device__ __forceinline__ void split2h(float x, float y, uint32_t& hi, uint32_t& lo) {
    __half2 h = __floats2half2_rn(x, y);
    float2 hf = __half22float2(h);
    __half2 l = __floats2half2_rn(x - hf.x, y - hf.y);
    hi = *(uint32_t*)&h;  lo = *(uint32_t*)&l;
}

// SW128 swizzle of (row, 16B-chunk) -> byte offset (128B rows)
__device__ __forceinline__ uint32_t swoff(int row, int c) {
    return (uint32_t)(row * 128 + ((c ^ (row & 7)) << 4));
}

// ---------------------------------------------------------------------------
// convert q (fp32) -> hi/lo fp16 pair
// ---------------------------------------------------------------------------
__global__ void convert_split_kernel(const float* __restrict__ x,
                                     __half* __restrict__ xh,
                                     __half* __restrict__ xl)
{
    int i = blockIdx.x * blockDim.x + threadIdx.x;   // i indexes float4
    float4 v = ((const float4*)x)[i];
    uint32_t h0, l0, h1, l1;
    split2h(v.x, v.y, h0, l0);
    split2h(v.z, v.w, h1, l1);
    uint32_t* ph = (uint32_t*)xh + i * 2;
    uint32_t* pl = (uint32_t*)xl + i * 2;
    ph[0] = h0; ph[1] = h1;
    pl[0] = l0; pl[1] = l1;
}

// ---------------------------------------------------------------------------
// weight transpose: W[k][n] fp32 -> Wt fp16 [n][k] (single)
// ---------------------------------------------------------------------------
__global__ void wconv_kernel(const float* __restrict__ W,
                             __half* __restrict__ Wt)
{
    __shared__ float t[32][33];
    int k = blockIdx.y * 32 + threadIdx.y;
    int n = blockIdx.x * 32 + threadIdx.x;
    t[threadIdx.y][threadIdx.x] = W[k * DD + n];
    __syncthreads();
    int nn = blockIdx.x * 32 + threadIdx.y;
    int kk = blockIdx.y * 32 + threadIdx.x;
    Wt[nn * DD + kk] = __float2half(t[threadIdx.x][threadIdx.y]);
}

// ---------------------------------------------------------------------------
// fp16 2-pass mma.sync GEMM: C = (Ah+Al)·Bh^T + bias.  A pair exact, B single.
// CTA 128x128, 8 warps (4m x 2n), warp 32x64, KC=64, 2-stage cp.async.
// OUTMODE=0: fp32 C[m][n].  OUTMODE=1: fp16 pair Ch/Cl.  OUTMODE=2: fp16 Ch.
// ---------------------------------------------------------------------------
#define KC        64
#define NCHUNK    (DD / KC)          // 16
#define TILE_B    16384              // 128 rows x 128 bytes
#define STG_B     (3 * TILE_B)       // 49152 (AH, AL, BH)
#define OFF_AH    0
#define OFF_AL    TILE_B
#define OFF_BH    (2 * TILE_B)
#define GEMM_SMEM (2 * STG_B)        // 98304
#define PADC      133

template <int OUTMODE>
__global__ __launch_bounds__(256)
void fp16x2_gemm_kernel(const __half* __restrict__ Ah,
                        const __half* __restrict__ Al,
                        const __half* __restrict__ Bh,
                        const float* __restrict__ bias,
                        float* __restrict__ C,
                        __half* __restrict__ Ch,
                        __half* __restrict__ Cl)
{
    extern __shared__ char smem[];
    const uint32_t sb = smem_to_u32(smem);
    const int tid  = threadIdx.x;
    const int wid  = tid >> 5;
    const int lane = tid & 31;

    const int n0 = blockIdx.x * 128;
    const int m0 = blockIdx.y * 128;

    const int m_base = (wid & 3) * 32;
    const int n_base = (wid >> 2) * 64;

    const __half* gAh = Ah + (size_t)m0 * DD;
    const __half* gAl = Al + (size_t)m0 * DD;
    const __half* gBh = Bh + (size_t)n0 * DD;

    const int f_row = tid >> 3;
    const int f_c   = tid & 7;

    float acc[2][8][4];
#pragma unroll
    for (int i = 0; i < 2; i++)
#pragma unroll
        for (int j = 0; j < 8; j++)
#pragma unroll
            for (int e = 0; e < 4; e++) acc[i][j][e] = 0.f;

    const int lane15 = lane & 15, laneHi = lane >> 4;
    int aRow[2], bRow[4];
#pragma unroll
    for (int i = 0; i < 2; i++) aRow[i] = m_base + i * 16 + lane15;
#pragma unroll
    for (int j = 0; j < 4; j++) bRow[j] = n_base + j * 16 + lane15;

    auto fill_stage = [&](int chunk, int stg) {
        const uint32_t base = sb + (uint32_t)stg * STG_B;
        const int k0 = chunk * KC;
#pragma unroll
        for (int r4 = 0; r4 < 4; r4++) {
            const int row = f_row + r4 * 32;
            const uint32_t so = swoff(row, f_c);
            const size_t go = (size_t)row * DD + k0 + f_c * 8;
            CP_ASYNC16(base + OFF_AH + so, gAh + go);
            CP_ASYNC16(base + OFF_AL + so, gAl + go);
            CP_ASYNC16(base + OFF_BH + so, gBh + go);
        }
    };

    fill_stage(0, 0);
    CP_COMMIT();

    for (int c = 0; c < NCHUNK; c++) {
        if (c + 1 < NCHUNK) {
            fill_stage(c + 1, (c + 1) & 1);
            CP_COMMIT();
            CP_WAIT1();
        } else {
            CP_WAIT0();
        }
        __syncthreads();

        const uint32_t base = sb + (uint32_t)(c & 1) * STG_B;
        const uint32_t bAH = base + OFF_AH, bAL = base + OFF_AL;
        const uint32_t bBH = base + OFF_BH;

#pragma unroll
        for (int ks = 0; ks < 4; ks++) {
            const int ch = ks * 2 + laneHi;
            uint32_t ah[2][4], al[2][4], bh[4][4];
#pragma unroll
            for (int i = 0; i < 2; i++) {
                const uint32_t ro = (uint32_t)(aRow[i] * 128);
                const uint32_t co = (uint32_t)((ch ^ (aRow[i] & 7)) << 4);
                ldsm4(ah[i], bAH + ro + co);
                ldsm4(al[i], bAL + ro + co);
            }
#pragma unroll
            for (int j = 0; j < 4; j++) {
                const uint32_t ro = (uint32_t)(bRow[j] * 128);
                const uint32_t co = (uint32_t)((ch ^ (bRow[j] & 7)) << 4);
                ldsm4(bh[j], bBH + ro + co);
            }
#pragma unroll
            for (int i = 0; i < 2; i++)
#pragma unroll
                for (int j = 0; j < 4; j++) {
                    mma16816(acc[i][2*j],   ah[i], bh[j][0], bh[j][2]);
                    mma16816(acc[i][2*j+1], ah[i], bh[j][1], bh[j][3]);
                    mma16816(acc[i][2*j],   al[i], bh[j][0], bh[j][2]);
                    mma16816(acc[i][2*j+1], al[i], bh[j][1], bh[j][3]);
                }
        }
        __syncthreads();
    }

    // ---- epilogue via padded smem tile ----
    float* ts = (float*)smem;
    float* sbias = (float*)smem + 128 * PADC;
    if (tid < 128) sbias[tid] = bias[n0 + tid];

    const int cr = lane >> 2, cc = (lane & 3) * 2;
#pragma unroll
    for (int i = 0; i < 2; i++) {
        const int r0 = m_base + i * 16 + cr;
#pragma unroll
        for (int j = 0; j < 8; j++) {
            const int cn = n_base + j * 8 + cc;
            ts[r0 * PADC + cn]           = acc[i][j][0];
            ts[r0 * PADC + cn + 1]       = acc[i][j][1];
            ts[(r0 + 8) * PADC + cn]     = acc[i][j][2];
            ts[(r0 + 8) * PADC + cn + 1] = acc[i][j][3];
        }
    }
    __syncthreads();

    if (OUTMODE == 0) {
#pragma unroll 4
        for (int it = 0; it < 64; it++) {
            const int idx = it * 256 + tid;
            const int m = idx >> 7, n = idx & 127;
            C[(size_t)(m0 + m) * DD + n0 + n] = ts[m * PADC + n] + sbias[n];
        }
    } else {
#pragma unroll 4
        for (int it = 0; it < 32; it++) {
            const int idx = it * 256 + tid;
            const int m = idx >> 6, n = (idx & 63) * 2;
            float x = ts[m * PADC + n]     + sbias[n];
            float y = ts[m * PADC + n + 1] + sbias[n + 1];
            const size_t o = (size_t)(m0 + m) * DD + n0 + n;
            if (OUTMODE == 1) {
                uint32_t hi, lo;
                split2h(x, y, hi, lo);
                *(uint32_t*)(Ch + o) = hi;
                *(uint32_t*)(Cl + o) = lo;
            } else {
                __half2 h = __floats2half2_rn(x, y);
                *(uint32_t*)(Ch + o) = *(uint32_t*)&h;
            }
        }
    }
}

// ---------------------------------------------------------------------------
// Causal flash attention on mma.sync, fp16 2-pass.
// QK = (Qh+Ql)·Kh; PV = (Ph+Pl)·Vh. BQ=BKV=128, 256 threads (8 warps x m16).
// smem: Qh/Ql 16KB each + 2 KV stages x (Kh,Vh 16KB each) = 96 KB.
// ---------------------------------------------------------------------------
#define FQH   0
#define FQL   16384
#define FKH   0
#define FVH   16384
#define FSTG(s) (32768 + (s) * 32768)
#define FLASH_SMEM 98304
#define SCL   0.18033688011112042f   /* 0.125 * log2(e) */

__global__ __launch_bounds__(256)
void flash_mma_kernel(const __half* __restrict__ Qh_,
                      const __half* __restrict__ Ql_,
                      const __half* __restrict__ Kh_,
                      const __half* __restrict__ Vh_,
                      __half* __restrict__ Oh,
                      __half* __restrict__ Ol)
{
    extern __shared__ char smem[];
    const uint32_t sb = smem_to_u32(smem);
    const int tid  = threadIdx.x;
    const int wid  = tid >> 5;
    const int lane = tid & 31;
    const int lane15 = lane & 15, laneHi = lane >> 4;
    const int cr = lane >> 2, cc = (lane & 3) * 2;

    const int qt = (int)gridDim.x - 1 - (int)blockIdx.x;   // heavy-first
    const int qb = qt * 128;
    const int h  = blockIdx.y;
    const int b  = blockIdx.z;

    const size_t hoff = (size_t)h * HS;
    const __half* gQh = Qh_ + (size_t)(b * SS + qb) * DD + hoff;
    const __half* gQl = Ql_ + (size_t)(b * SS + qb) * DD + hoff;
    const __half* gKh = Kh_ + (size_t)(b * SS) * DD + hoff;
    const __half* gVh = Vh_ + (size_t)(b * SS) * DD + hoff;

    const int f_row = tid >> 3;     // 0..31
    const int f_c   = tid & 7;

    // fill Q (once)
#pragma unroll
    for (int r4 = 0; r4 < 4; r4++) {
        const int row = f_row + r4 * 32;
        const uint32_t so = swoff(row, f_c);
        const size_t go = (size_t)row * DD + f_c * 8;
        CP_ASYNC16(sb + FQH + so, gQh + go);
        CP_ASYNC16(sb + FQL + so, gQl + go);
    }
    auto fill_kv = [&](int kb, int st) {
        const uint32_t base = sb + FSTG(st);
#pragma unroll
        for (int r4 = 0; r4 < 4; r4++) {
            const int row = f_row + r4 * 32;
            const uint32_t so = swoff(row, f_c);
            const size_t go = (size_t)(kb + row) * DD + f_c * 8;
            CP_ASYNC16(base + FKH + so, gKh + go);
            CP_ASYNC16(base + FVH + so, gVh + go);
        }
    };
    fill_kv(0, 0);
    CP_COMMIT();

    uint32_t qfh[4][4], qfl[4][4];
    float o[8][4];
#pragma unroll
    for (int j = 0; j < 8; j++)
#pragma unroll
        for (int e = 0; e < 4; e++) o[j][e] = 0.f;
    float m0 = -INFINITY, m1 = -INFINITY, l0 = 0.f, l1 = 0.f;

    // V ldsm row (per lane, fixed across loop)
    const int vrow_lane = (lane & 7) + 8 * ((lane >> 3) & 1);
    const int vchunk_hi = lane >> 4;     // +0/+1 chunk

    for (int c = 0; c <= qt; c++) {
        if (c < qt) {
            fill_kv((c + 1) * 128, (c + 1) & 1);
            CP_COMMIT();
            CP_WAIT1();
        } else {
            CP_WAIT0();
        }
        __syncthreads();

        if (c == 0) {
            // Q fragments: row-major A frags, register resident
            const int qr = wid * 16 + lane15;
            const uint32_t ro = (uint32_t)(qr * 128);
            const int sw = qr & 7;
#pragma unroll
            for (int ks = 0; ks < 4; ks++) {
                const int ch = ks * 2 + laneHi;
                const uint32_t co = (uint32_t)((ch ^ sw) << 4);
                ldsm4(qfh[ks], sb + FQH + ro + co);
                ldsm4(qfl[ks], sb + FQL + ro + co);
            }
        }

        const uint32_t base = sb + FSTG(c & 1);

        // ---- scores: (Qh+Ql)·Kh ----
        float acc[16][4];
#pragma unroll
        for (int j = 0; j < 16; j++)
#pragma unroll
            for (int e = 0; e < 4; e++) acc[j][e] = 0.f;

#pragma unroll
        for (int ks = 0; ks < 4; ks++) {
            const int ch = ks * 2 + laneHi;
#pragma unroll
            for (int j = 0; j < 8; j++) {
                const int br = j * 16 + lane15;
                const uint32_t off = (uint32_t)(br * 128 + ((ch ^ (br & 7)) << 4));
                uint32_t kh[4];
                ldsm4(kh, base + FKH + off);
                mma16816(acc[2*j],   qfh[ks], kh[0], kh[2]);
                mma16816(acc[2*j+1], qfh[ks], kh[1], kh[3]);
                mma16816(acc[2*j],   qfl[ks], kh[0], kh[2]);
                mma16816(acc[2*j+1], qfl[ks], kh[1], kh[3]);
            }
        }

        // ---- causal mask (diagonal tile) ----
        if (c == qt) {
            const int qr0 = wid * 16 + cr;
#pragma unroll
            for (int j = 0; j < 16; j++) {
                const int col = j * 8 + cc;
                if (col     > qr0)     acc[j][0] = -INFINITY;
                if (col + 1 > qr0)     acc[j][1] = -INFINITY;
                if (col     > qr0 + 8) acc[j][2] = -INFINITY;
                if (col + 1 > qr0 + 8) acc[j][3] = -INFINITY;
            }
        }

        // ---- online softmax (fp32, scale folded into exp2) ----
        float mx0 = -INFINITY, mx1 = -INFINITY;
#pragma unroll
        for (int j = 0; j < 16; j++) {
            mx0 = fmaxf(mx0, fmaxf(acc[j][0], acc[j][1]));
            mx1 = fmaxf(mx1, fmaxf(acc[j][2], acc[j][3]));
        }
        mx0 = fmaxf(mx0, __shfl_xor_sync(0xffffffffu, mx0, 1));
        mx0 = fmaxf(mx0, __shfl_xor_sync(0xffffffffu, mx0, 2));
        mx1 = fmaxf(mx1, __shfl_xor_sync(0xffffffffu, mx1, 1));
        mx1 = fmaxf(mx1, __shfl_xor_sync(0xffffffffu, mx1, 2));
        const float mn0 = fmaxf(m0, mx0);
        const float mn1 = fmaxf(m1, mx1);
        const float a0 = fexp2((m0 - mn0) * SCL);
        const float a1 = fexp2((m1 - mn1) * SCL);
        m0 = mn0; m1 = mn1;
        float rs0 = 0.f, rs1 = 0.f;
#pragma unroll
        for (int j = 0; j < 16; j++) {
            acc[j][0] = fexp2((acc[j][0] - mn0) * SCL);
            acc[j][1] = fexp2((acc[j][1] - mn0) * SCL);
            acc[j][2] = fexp2((acc[j][2] - mn1) * SCL);
            acc[j][3] = fexp2((acc[j][3] - mn1) * SCL);
            rs0 += acc[j][0] + acc[j][1];
            rs1 += acc[j][2] + acc[j][3];
        }
        rs0 += __shfl_xor_sync(0xffffffffu, rs0, 1);
        rs0 += __shfl_xor_sync(0xffffffffu, rs0, 2);
        rs1 += __shfl_xor_sync(0xffffffffu, rs1, 1);
        rs1 += __shfl_xor_sync(0xffffffffu, rs1, 2);
        l0 = l0 * a0 + rs0;
        l1 = l1 * a1 + rs1;
#pragma unroll
        for (int j = 0; j < 8; j++) {
            o[j][0] *= a0; o[j][1] *= a0;
            o[j][2] *= a1; o[j][3] *= a1;
        }

        // ---- PV: (Ph+Pl)·Vh, P frags straight from score regs ----
#pragma unroll
        for (int t = 0; t < 8; t++) {
            uint32_t Ap[4], Alo[4];
            split2h(acc[2*t][0],   acc[2*t][1],   Ap[0], Alo[0]);
            split2h(acc[2*t][2],   acc[2*t][3],   Ap[1], Alo[1]);
            split2h(acc[2*t+1][0], acc[2*t+1][1], Ap[2], Alo[2]);
            split2h(acc[2*t+1][2], acc[2*t+1][3], Ap[3], Alo[3]);
            const int vr = t * 16 + vrow_lane;
            const uint32_t tro = (uint32_t)(vr * 128);
            const int tsw = vr & 7;
#pragma unroll
            for (int nt = 0; nt < 4; nt++) {
                const int chv = nt * 2 + vchunk_hi;
                const uint32_t voff = tro + (uint32_t)((chv ^ tsw) << 4);
                uint32_t vh[4];
                ldsm4t(vh, base + FVH + voff);
                mma16816(o[2*nt],   Ap,  vh[0], vh[1]);
                mma16816(o[2*nt+1], Ap,  vh[2], vh[3]);
                mma16816(o[2*nt],   Alo, vh[0], vh[1]);
                mma16816(o[2*nt+1], Alo, vh[2], vh[3]);
            }
        }
        __syncthreads();
    }

    // ---- epilogue: normalize + split fp16 hi/lo, natural layout ----
    const float inv0 = 1.f / l0;
    const float inv1 = 1.f / l1;
    const int q0 = qb + wid * 16 + cr;
    const size_t r0o = (size_t)(b * SS + q0) * DD + (size_t)h * HS;
    const size_t r1o = r0o + (size_t)8 * DD;
#pragma unroll
    for (int j = 0; j < 8; j++) {
        const int d = j * 8 + cc;
        uint32_t hi, lo;
        split2h(o[j][0] * inv0, o[j][1] * inv0, hi, lo);
        *(uint32_t*)(Oh + r0o + d) = hi;
        *(uint32_t*)(Ol + r0o + d) = lo;
        split2h(o[j][2] * inv1, o[j][3] * inv1, hi, lo);
        *(uint32_t*)(Oh + r1o + d) = hi;
        *(uint32_t*)(Ol + r1o + d) = lo;
    }
}

// ---------------------------------------------------------------------------
extern "C" void kernel_launch(void* const* d_in, const int* in_sizes, int n_in,
                              void* d_out, int out_size)
{
    const float* q  = (const float*)d_in[0];
    const float* Wq = (const float*)d_in[1];
    const float* bq = (const float*)d_in[2];
    const float* Wk = (const float*)d_in[3];
    const float* bk = (const float*)d_in[4];
    const float* Wv = (const float*)d_in[5];
    const float* bv = (const float*)d_in[6];
    const float* Wo = (const float*)d_in[7];
    const float* bo = (const float*)d_in[8];

    __half *qh, *ql, *Qph, *Qpl, *Kh, *Vh, *Ath, *Atl;
    __half *Wqc, *Wkc, *Wvc, *Woc;
    cudaGetSymbolAddress((void**)&qh,  g_qh);
    cudaGetSymbolAddress((void**)&ql,  g_ql);
    cudaGetSymbolAddress((void**)&Qph, g_Qph);
    cudaGetSymbolAddress((void**)&Qpl, g_Qpl);
    cudaGetSymbolAddress((void**)&Kh,  g_Kh);
    cudaGetSymbolAddress((void**)&Vh,  g_Vh);
    cudaGetSymbolAddress((void**)&Ath, g_Ath);
    cudaGetSymbolAddress((void**)&Atl, g_Atl);
    cudaGetSymbolAddress((void**)&Wqc, g_Wq);
    cudaGetSymbolAddress((void**)&Wkc, g_Wk);
    cudaGetSymbolAddress((void**)&Wvc, g_Wv);
    cudaGetSymbolAddress((void**)&Woc, g_Wo);

    cudaFuncSetAttribute(flash_mma_kernel,
                         cudaFuncAttributeMaxDynamicSharedMemorySize, FLASH_SMEM);
    cudaFuncSetAttribute(fp16x2_gemm_kernel<0>,
                         cudaFuncAttributeMaxDynamicSharedMemorySize, GEMM_SMEM);
    cudaFuncSetAttribute(fp16x2_gemm_kernel<1>,
                         cudaFuncAttributeMaxDynamicSharedMemorySize, GEMM_SMEM);
    cudaFuncSetAttribute(fp16x2_gemm_kernel<2>,
                         cudaFuncAttributeMaxDynamicSharedMemorySize, GEMM_SMEM);

    // 1. input + weight conversions
    convert_split_kernel<<<4096, 256>>>(q, qh, ql);
    dim3 wgrid(32, 32), wblk(32, 32);
    wconv_kernel<<<wgrid, wblk>>>(Wq, Wqc);
    wconv_kernel<<<wgrid, wblk>>>(Wk, Wkc);
    wconv_kernel<<<wgrid, wblk>>>(Wv, Wvc);
    wconv_kernel<<<wgrid, wblk>>>(Wo, Woc);

    // 2. projections (fp16 2-pass)
    dim3 ggrid(DD / 128, MM / 128);   // (8, 32)
    fp16x2_gemm_kernel<1><<<ggrid, 256, GEMM_SMEM>>>(qh, ql, Wqc, bq,
                                                     nullptr, Qph, Qpl);
    fp16x2_gemm_kernel<2><<<ggrid, 256, GEMM_SMEM>>>(qh, ql, Wkc, bk,
                                                     nullptr, Kh, nullptr);
    fp16x2_gemm_kernel<2><<<ggrid, 256, GEMM_SMEM>>>(qh, ql, Wvc, bv,
                                                     nullptr, Vh, nullptr);

    // 3. attention (fp16 2-pass mma)
    flash_mma_kernel<<<dim3(SS / 128, HH, BB), 256, FLASH_SMEM>>>(
        Qph, Qpl, Kh, Vh, Ath, Atl);

    // 4. output projection (fp32 out)
    fp16x2_gemm_kernel<0><<<ggrid, 256, GEMM_SMEM>>>(Ath, Atl, Woc, bo,
                                                     (float*)d_out, nullptr, nullptr);
}

// round 9
// speedup vs baseline: 4.6353x; 1.3915x over previous
#include <cuda_runtime.h>
#include <cuda_fp16.h>
#include <math.h>
#include <stdint.h>

// Problem constants
#define BB   2
#define SS   2048
#define DD   1024
#define HH   16
#define HS   64
#define MM   (BB * SS)     // 4096

// ---------------------------------------------------------------------------
// Scratch (device globals: allocation-free rule)
// ---------------------------------------------------------------------------
__device__ __half  g_qh[MM * DD], g_ql[MM * DD];     // input q split (pair)
__device__ __half  g_Qh[MM * DD];                    // projected Q (single)
__device__ __half  g_Kh[MM * DD];                    // projected K (single)
__device__ __half  g_Vh[MM * DD];                    // projected V (single)
__device__ __half  g_Ath[MM * DD];                   // attention out (single)
__device__ __half  g_Wq[DD * DD], g_Wk[DD * DD];     // transposed W (single)
__device__ __half  g_Wv[DD * DD], g_Wo[DD * DD];

// ---------------------------------------------------------------------------
// Helpers (family-portable PTX only: ldmatrix / mma.sync / cp.async)
// ---------------------------------------------------------------------------
__device__ __forceinline__ uint32_t smem_to_u32(const void* p) {
    uint32_t a;
    asm("{ .reg .u64 t; cvta.to.shared.u64 t, %1; cvt.u32.u64 %0, t; }"
        : "=r"(a) : "l"(p));
    return a;
}
__device__ __forceinline__ void ldsm4(uint32_t (&r)[4], uint32_t addr) {
    asm volatile("ldmatrix.sync.aligned.m8n8.x4.shared.b16 {%0,%1,%2,%3}, [%4];"
                 : "=r"(r[0]), "=r"(r[1]), "=r"(r[2]), "=r"(r[3]) : "r"(addr));
}
__device__ __forceinline__ void ldsm4t(uint32_t (&r)[4], uint32_t addr) {
    asm volatile("ldmatrix.sync.aligned.m8n8.x4.trans.shared.b16 {%0,%1,%2,%3}, [%4];"
                 : "=r"(r[0]), "=r"(r[1]), "=r"(r[2]), "=r"(r[3]) : "r"(addr));
}
__device__ __forceinline__ void mma16816(float (&d)[4], const uint32_t (&a)[4],
                                         uint32_t b0, uint32_t b1) {
    asm volatile(
        "mma.sync.aligned.m16n8k16.row.col.f32.f16.f16.f32 "
        "{%0,%1,%2,%3}, {%4,%5,%6,%7}, {%8,%9}, {%0,%1,%2,%3};"
        : "+f"(d[0]), "+f"(d[1]), "+f"(d[2]), "+f"(d[3])
        : "r"(a[0]), "r"(a[1]), "r"(a[2]), "r"(a[3]), "r"(b0), "r"(b1));
}
#define CP_ASYNC16(dst, src) \
    asm volatile("cp.async.cg.shared.global [%0], [%1], 16;" :: "r"(dst), "l"(src))
#define CP_COMMIT() asm volatile("cp.async.commit_group;" ::: "memory")
#define CP_WAIT1()  asm volatile("cp.async.wait_group 1;" ::: "memory")
#define CP_WAIT0()  asm volatile("cp.async.wait_group 0;" ::: "memory")

__device__ __forceinline__ float fexp2(float x) {
    float r;
    asm("ex2.approx.f32 %0, %1;" : "=f"(r) : "f"(x));
    return r;
}
// pack (x,y) -> half2 hi + residual half2 lo (as u32)
__device__ __forceinline__ void split2h(float x, float y, uint32_t& hi, uint32_t& lo) {
    __half2 h = __floats2half2_rn(x, y);
    float2 hf = __half22float2(h);
    __half2 l = __floats2half2_rn(x - hf.x, y - hf.y);
    hi = *(uint32_t*)&h;  lo = *(uint32_t*)&l;
}

// SW128 swizzle of (row, 16B-chunk) -> byte offset (128B rows)
__device__ __forceinline__ uint32_t swoff(int row, int c) {
    return (uint32_t)(row * 128 + ((c ^ (row & 7)) << 4));
}

// ---------------------------------------------------------------------------
// convert q (fp32) -> hi/lo fp16 pair
// ---------------------------------------------------------------------------
__global__ void convert_split_kernel(const float* __restrict__ x,
                                     __half* __restrict__ xh,
                                     __half* __restrict__ xl)
{
    int i = blockIdx.x * blockDim.x + threadIdx.x;   // i indexes float4
    float4 v = ((const float4*)x)[i];
    uint32_t h0, l0, h1, l1;
    split2h(v.x, v.y, h0, l0);
    split2h(v.z, v.w, h1, l1);
    uint32_t* ph = (uint32_t*)xh + i * 2;
    uint32_t* pl = (uint32_t*)xl + i * 2;
    ph[0] = h0; ph[1] = h1;
    pl[0] = l0; pl[1] = l1;
}

// ---------------------------------------------------------------------------
// fused weight transpose: 4x W[k][n] fp32 -> Wt fp16 [n][k] (blockIdx.z picks)
// ---------------------------------------------------------------------------
__global__ void wconv4_kernel(const float* __restrict__ W0, __half* __restrict__ T0,
                              const float* __restrict__ W1, __half* __restrict__ T1,
                              const float* __restrict__ W2, __half* __restrict__ T2,
                              const float* __restrict__ W3, __half* __restrict__ T3)
{
    const float* W = (blockIdx.z == 0) ? W0 : (blockIdx.z == 1) ? W1
                   : (blockIdx.z == 2) ? W2 : W3;
    __half* Wt     = (blockIdx.z == 0) ? T0 : (blockIdx.z == 1) ? T1
                   : (blockIdx.z == 2) ? T2 : T3;
    __shared__ float t[32][33];
    int k = blockIdx.y * 32 + threadIdx.y;
    int n = blockIdx.x * 32 + threadIdx.x;
    t[threadIdx.y][threadIdx.x] = W[k * DD + n];
    __syncthreads();
    int nn = blockIdx.x * 32 + threadIdx.y;
    int kk = blockIdx.y * 32 + threadIdx.x;
    Wt[nn * DD + kk] = __float2half(t[threadIdx.x][threadIdx.y]);
}

// ---------------------------------------------------------------------------
// fp16 mma.sync GEMM: C = (Ah[+Al])·Bh^T + bias.
// APASS=1: A single.  APASS=2: A hi/lo pair (2 MMA passes).
// OUTMODE=0: fp32 C.  OUTMODE=2: fp16 Ch single.
// CTA 128x128, 8 warps (4m x 2n), KC=64, 2-stage cp.async.
// ---------------------------------------------------------------------------
#define KC        64
#define NCHUNK    (DD / KC)          // 16
#define TILE_B    16384              // 128 rows x 128 bytes
#define PADC      133
#define GEMM_SMEM1 69632             // max(2*2*TILE_B, epilogue 68608)
#define GEMM_SMEM2 98304             // 2*3*TILE_B

template <int APASS, int OUTMODE>
__global__ __launch_bounds__(256)
void fp16_gemm_kernel(const __half* __restrict__ Ah,
                      const __half* __restrict__ Al,
                      const __half* __restrict__ Bh,
                      const float* __restrict__ bias,
                      float* __restrict__ C,
                      __half* __restrict__ Ch)
{
    constexpr int STG_B  = (APASS + 1) * TILE_B;
    constexpr int OFF_AL = TILE_B;                 // valid when APASS==2
    constexpr int OFF_BH = APASS * TILE_B;

    extern __shared__ char smem[];
    const uint32_t sb = smem_to_u32(smem);
    const int tid  = threadIdx.x;
    const int wid  = tid >> 5;
    const int lane = tid & 31;

    const int n0 = blockIdx.x * 128;
    const int m0 = blockIdx.y * 128;

    const int m_base = (wid & 3) * 32;
    const int n_base = (wid >> 2) * 64;

    const __half* gAh = Ah + (size_t)m0 * DD;
    const __half* gAl = (APASS == 2) ? (Al + (size_t)m0 * DD) : nullptr;
    const __half* gBh = Bh + (size_t)n0 * DD;

    const int f_row = tid >> 3;
    const int f_c   = tid & 7;

    float acc[2][8][4];
#pragma unroll
    for (int i = 0; i < 2; i++)
#pragma unroll
        for (int j = 0; j < 8; j++)
#pragma unroll
            for (int e = 0; e < 4; e++) acc[i][j][e] = 0.f;

    const int lane15 = lane & 15, laneHi = lane >> 4;
    int aRow[2], bRow[4];
#pragma unroll
    for (int i = 0; i < 2; i++) aRow[i] = m_base + i * 16 + lane15;
#pragma unroll
    for (int j = 0; j < 4; j++) bRow[j] = n_base + j * 16 + lane15;

    auto fill_stage = [&](int chunk, int stg) {
        const uint32_t base = sb + (uint32_t)stg * STG_B;
        const int k0 = chunk * KC;
#pragma unroll
        for (int r4 = 0; r4 < 4; r4++) {
            const int row = f_row + r4 * 32;
            const uint32_t so = swoff(row, f_c);
            const size_t go = (size_t)row * DD + k0 + f_c * 8;
            CP_ASYNC16(base + so, gAh + go);
            if (APASS == 2) CP_ASYNC16(base + OFF_AL + so, gAl + go);
            CP_ASYNC16(base + OFF_BH + so, gBh + go);
        }
    };

    fill_stage(0, 0);
    CP_COMMIT();

    for (int c = 0; c < NCHUNK; c++) {
        if (c + 1 < NCHUNK) {
            fill_stage(c + 1, (c + 1) & 1);
            CP_COMMIT();
            CP_WAIT1();
        } else {
            CP_WAIT0();
        }
        __syncthreads();

        const uint32_t base = sb + (uint32_t)(c & 1) * STG_B;

#pragma unroll
        for (int ks = 0; ks < 4; ks++) {
            const int ch = ks * 2 + laneHi;
            uint32_t ah[2][4], al[2][4], bh[4][4];
#pragma unroll
            for (int i = 0; i < 2; i++) {
                const uint32_t ro = (uint32_t)(aRow[i] * 128);
                const uint32_t co = (uint32_t)((ch ^ (aRow[i] & 7)) << 4);
                ldsm4(ah[i], base + ro + co);
                if (APASS == 2) ldsm4(al[i], base + OFF_AL + ro + co);
            }
#pragma unroll
            for (int j = 0; j < 4; j++) {
                const uint32_t ro = (uint32_t)(bRow[j] * 128);
                const uint32_t co = (uint32_t)((ch ^ (bRow[j] & 7)) << 4);
                ldsm4(bh[j], base + OFF_BH + ro + co);
            }
#pragma unroll
            for (int i = 0; i < 2; i++)
#pragma unroll
                for (int j = 0; j < 4; j++) {
                    mma16816(acc[i][2*j],   ah[i], bh[j][0], bh[j][2]);
                    mma16816(acc[i][2*j+1], ah[i], bh[j][1], bh[j][3]);
                    if (APASS == 2) {
                        mma16816(acc[i][2*j],   al[i], bh[j][0], bh[j][2]);
                        mma16816(acc[i][2*j+1], al[i], bh[j][1], bh[j][3]);
                    }
                }
        }
        __syncthreads();
    }

    // ---- epilogue via padded smem tile ----
    float* ts = (float*)smem;
    float* sbias = (float*)smem + 128 * PADC;
    if (tid < 128) sbias[tid] = bias[n0 + tid];

    const int cr = lane >> 2, cc = (lane & 3) * 2;
#pragma unroll
    for (int i = 0; i < 2; i++) {
        const int r0 = m_base + i * 16 + cr;
#pragma unroll
        for (int j = 0; j < 8; j++) {
            const int cn = n_base + j * 8 + cc;
            ts[r0 * PADC + cn]           = acc[i][j][0];
            ts[r0 * PADC + cn + 1]       = acc[i][j][1];
            ts[(r0 + 8) * PADC + cn]     = acc[i][j][2];
            ts[(r0 + 8) * PADC + cn + 1] = acc[i][j][3];
        }
    }
    __syncthreads();

    if (OUTMODE == 0) {
#pragma unroll 4
        for (int it = 0; it < 64; it++) {
            const int idx = it * 256 + tid;
            const int m = idx >> 7, n = idx & 127;
            C[(size_t)(m0 + m) * DD + n0 + n] = ts[m * PADC + n] + sbias[n];
        }
    } else {
#pragma unroll 4
        for (int it = 0; it < 32; it++) {
            const int idx = it * 256 + tid;
            const int m = idx >> 6, n = (idx & 63) * 2;
            float x = ts[m * PADC + n]     + sbias[n];
            float y = ts[m * PADC + n + 1] + sbias[n + 1];
            const size_t o = (size_t)(m0 + m) * DD + n0 + n;
            __half2 h = __floats2half2_rn(x, y);
            *(uint32_t*)(Ch + o) = *(uint32_t*)&h;
        }
    }
}

// ---------------------------------------------------------------------------
// Causal flash attention on mma.sync.
// QK = Qh·Kh (single pass); PV = (Ph+Pl)·Vh (pair, direct path protected).
// BQ=BKV=128, 256 threads (8 warps x m16). Q frags register-resident.
// smem: Qh 16KB + 2 KV stages x (Kh,Vh 16KB each) = 80 KB -> occ 2.
// ---------------------------------------------------------------------------
#define FQH   0
#define FKH   0
#define FVH   16384
#define FSTG(s) (16384 + (s) * 32768)
#define FLASH_SMEM 81920
#define SCL   0.18033688011112042f   /* 0.125 * log2(e) */

__global__ __launch_bounds__(256)
void flash_mma_kernel(const __half* __restrict__ Qh_,
                      const __half* __restrict__ Kh_,
                      const __half* __restrict__ Vh_,
                      __half* __restrict__ Oh)
{
    extern __shared__ char smem[];
    const uint32_t sb = smem_to_u32(smem);
    const int tid  = threadIdx.x;
    const int wid  = tid >> 5;
    const int lane = tid & 31;
    const int lane15 = lane & 15, laneHi = lane >> 4;
    const int cr = lane >> 2, cc = (lane & 3) * 2;

    const int qt = (int)gridDim.x - 1 - (int)blockIdx.x;   // heavy-first
    const int qb = qt * 128;
    const int h  = blockIdx.y;
    const int b  = blockIdx.z;

    const size_t hoff = (size_t)h * HS;
    const __half* gQh = Qh_ + (size_t)(b * SS + qb) * DD + hoff;
    const __half* gKh = Kh_ + (size_t)(b * SS) * DD + hoff;
    const __half* gVh = Vh_ + (size_t)(b * SS) * DD + hoff;

    const int f_row = tid >> 3;     // 0..31
    const int f_c   = tid & 7;

    // fill Q (once)
#pragma unroll
    for (int r4 = 0; r4 < 4; r4++) {
        const int row = f_row + r4 * 32;
        const uint32_t so = swoff(row, f_c);
        CP_ASYNC16(sb + FQH + so, gQh + (size_t)row * DD + f_c * 8);
    }
    auto fill_kv = [&](int kb, int st) {
        const uint32_t base = sb + FSTG(st);
#pragma unroll
        for (int r4 = 0; r4 < 4; r4++) {
            const int row = f_row + r4 * 32;
            const uint32_t so = swoff(row, f_c);
            const size_t go = (size_t)(kb + row) * DD + f_c * 8;
            CP_ASYNC16(base + FKH + so, gKh + go);
            CP_ASYNC16(base + FVH + so, gVh + go);
        }
    };
    fill_kv(0, 0);
    CP_COMMIT();

    uint32_t qfh[4][4];
    float o[8][4];
#pragma unroll
    for (int j = 0; j < 8; j++)
#pragma unroll
        for (int e = 0; e < 4; e++) o[j][e] = 0.f;
    float m0 = -INFINITY, m1 = -INFINITY, l0 = 0.f, l1 = 0.f;

    // V ldsm row (per lane, fixed across loop)
    const int vrow_lane = (lane & 7) + 8 * ((lane >> 3) & 1);
    const int vchunk_hi = lane >> 4;     // +0/+1 chunk

    for (int c = 0; c <= qt; c++) {
        if (c < qt) {
            fill_kv((c + 1) * 128, (c + 1) & 1);
            CP_COMMIT();
            CP_WAIT1();
        } else {
            CP_WAIT0();
        }
        __syncthreads();

        if (c == 0) {
            // Q fragments: row-major A frags, register resident
            const int qr = wid * 16 + lane15;
            const uint32_t ro = (uint32_t)(qr * 128);
            const int sw = qr & 7;
#pragma unroll
            for (int ks = 0; ks < 4; ks++) {
                const int ch = ks * 2 + laneHi;
                ldsm4(qfh[ks], sb + FQH + ro + (uint32_t)((ch ^ sw) << 4));
            }
        }

        const uint32_t base = sb + FSTG(c & 1);

        // ---- scores: Qh·Kh (single pass) ----
        float acc[16][4];
#pragma unroll
        for (int j = 0; j < 16; j++)
#pragma unroll
            for (int e = 0; e < 4; e++) acc[j][e] = 0.f;

#pragma unroll
        for (int ks = 0; ks < 4; ks++) {
            const int ch = ks * 2 + laneHi;
#pragma unroll
            for (int j = 0; j < 8; j++) {
                const int br = j * 16 + lane15;
                const uint32_t off = (uint32_t)(br * 128 + ((ch ^ (br & 7)) << 4));
                uint32_t kh[4];
                ldsm4(kh, base + FKH + off);
                mma16816(acc[2*j],   qfh[ks], kh[0], kh[2]);
                mma16816(acc[2*j+1], qfh[ks], kh[1], kh[3]);
            }
        }

        // ---- causal mask (diagonal tile) ----
        if (c == qt) {
            const int qr0 = wid * 16 + cr;
#pragma unroll
            for (int j = 0; j < 16; j++) {
                const int col = j * 8 + cc;
                if (col     > qr0)     acc[j][0] = -INFINITY;
                if (col + 1 > qr0)     acc[j][1] = -INFINITY;
                if (col     > qr0 + 8) acc[j][2] = -INFINITY;
                if (col + 1 > qr0 + 8) acc[j][3] = -INFINITY;
            }
        }

        // ---- online softmax (fp32, scale folded into exp2) ----
        float mx0 = -INFINITY, mx1 = -INFINITY;
#pragma unroll
        for (int j = 0; j < 16; j++) {
            mx0 = fmaxf(mx0, fmaxf(acc[j][0], acc[j][1]));
            mx1 = fmaxf(mx1, fmaxf(acc[j][2], acc[j][3]));
        }
        mx0 = fmaxf(mx0, __shfl_xor_sync(0xffffffffu, mx0, 1));
        mx0 = fmaxf(mx0, __shfl_xor_sync(0xffffffffu, mx0, 2));
        mx1 = fmaxf(mx1, __shfl_xor_sync(0xffffffffu, mx1, 1));
        mx1 = fmaxf(mx1, __shfl_xor_sync(0xffffffffu, mx1, 2));
        const float mn0 = fmaxf(m0, mx0);
        const float mn1 = fmaxf(m1, mx1);
        const float a0 = fexp2((m0 - mn0) * SCL);
        const float a1 = fexp2((m1 - mn1) * SCL);
        m0 = mn0; m1 = mn1;
        float rs0 = 0.f, rs1 = 0.f;
#pragma unroll
        for (int j = 0; j < 16; j++) {
            acc[j][0] = fexp2((acc[j][0] - mn0) * SCL);
            acc[j][1] = fexp2((acc[j][1] - mn0) * SCL);
            acc[j][2] = fexp2((acc[j][2] - mn1) * SCL);
            acc[j][3] = fexp2((acc[j][3] - mn1) * SCL);
            rs0 += acc[j][0] + acc[j][1];
            rs1 += acc[j][2] + acc[j][3];
        }
        rs0 += __shfl_xor_sync(0xffffffffu, rs0, 1);
        rs0 += __shfl_xor_sync(0xffffffffu, rs0, 2);
        rs1 += __shfl_xor_sync(0xffffffffu, rs1, 1);
        rs1 += __shfl_xor_sync(0xffffffffu, rs1, 2);
        l0 = l0 * a0 + rs0;
        l1 = l1 * a1 + rs1;
#pragma unroll
        for (int j = 0; j < 8; j++) {
            o[j][0] *= a0; o[j][1] *= a0;
            o[j][2] *= a1; o[j][3] *= a1;
        }

        // ---- PV: (Ph+Pl)·Vh, P frags straight from score regs ----
#pragma unroll
        for (int t = 0; t < 8; t++) {
            uint32_t Ap[4], Alo[4];
            split2h(acc[2*t][0],   acc[2*t][1],   Ap[0], Alo[0]);
            split2h(acc[2*t][2],   acc[2*t][3],   Ap[1], Alo[1]);
            split2h(acc[2*t+1][0], acc[2*t+1][1], Ap[2], Alo[2]);
            split2h(acc[2*t+1][2], acc[2*t+1][3], Ap[3], Alo[3]);
            const int vr = t * 16 + vrow_lane;
            const uint32_t tro = (uint32_t)(vr * 128);
            const int tsw = vr & 7;
#pragma unroll
            for (int nt = 0; nt < 4; nt++) {
                const int chv = nt * 2 + vchunk_hi;
                const uint32_t voff = tro + (uint32_t)((chv ^ tsw) << 4);
                uint32_t vh[4];
                ldsm4t(vh, base + FVH + voff);
                mma16816(o[2*nt],   Ap,  vh[0], vh[1]);
                mma16816(o[2*nt+1], Ap,  vh[2], vh[3]);
                mma16816(o[2*nt],   Alo, vh[0], vh[1]);
                mma16816(o[2*nt+1], Alo, vh[2], vh[3]);
            }
        }
        __syncthreads();
    }

    // ---- epilogue: normalize + single fp16, natural layout ----
    const float inv0 = 1.f / l0;
    const float inv1 = 1.f / l1;
    const int q0 = qb + wid * 16 + cr;
    const size_t r0o = (size_t)(b * SS + q0) * DD + (size_t)h * HS;
    const size_t r1o = r0o + (size_t)8 * DD;
#pragma unroll
    for (int j = 0; j < 8; j++) {
        const int d = j * 8 + cc;
        __half2 h0 = __floats2half2_rn(o[j][0] * inv0, o[j][1] * inv0);
        __half2 h1 = __floats2half2_rn(o[j][2] * inv1, o[j][3] * inv1);
        *(uint32_t*)(Oh + r0o + d) = *(uint32_t*)&h0;
        *(uint32_t*)(Oh + r1o + d) = *(uint32_t*)&h1;
    }
}

// ---------------------------------------------------------------------------
extern "C" void kernel_launch(void* const* d_in, const int* in_sizes, int n_in,
                              void* d_out, int out_size)
{
    const float* q  = (const float*)d_in[0];
    const float* Wq = (const float*)d_in[1];
    const float* bq = (const float*)d_in[2];
    const float* Wk = (const float*)d_in[3];
    const float* bk = (const float*)d_in[4];
    const float* Wv = (const float*)d_in[5];
    const float* bv = (const float*)d_in[6];
    const float* Wo = (const float*)d_in[7];
    const float* bo = (const float*)d_in[8];

    __half *qh, *ql, *Qh, *Kh, *Vh, *Ath;
    __half *Wqc, *Wkc, *Wvc, *Woc;
    cudaGetSymbolAddress((void**)&qh,  g_qh);
    cudaGetSymbolAddress((void**)&ql,  g_ql);
    cudaGetSymbolAddress((void**)&Qh,  g_Qh);
    cudaGetSymbolAddress((void**)&Kh,  g_Kh);
    cudaGetSymbolAddress((void**)&Vh,  g_Vh);
    cudaGetSymbolAddress((void**)&Ath, g_Ath);
    cudaGetSymbolAddress((void**)&Wqc, g_Wq);
    cudaGetSymbolAddress((void**)&Wkc, g_Wk);
    cudaGetSymbolAddress((void**)&Wvc, g_Wv);
    cudaGetSymbolAddress((void**)&Woc, g_Wo);

    cudaFuncSetAttribute(flash_mma_kernel,
                         cudaFuncAttributeMaxDynamicSharedMemorySize, FLASH_SMEM);
    cudaFuncSetAttribute(fp16_gemm_kernel<1, 0>,
                         cudaFuncAttributeMaxDynamicSharedMemorySize, GEMM_SMEM1);
    cudaFuncSetAttribute(fp16_gemm_kernel<1, 2>,
                         cudaFuncAttributeMaxDynamicSharedMemorySize, GEMM_SMEM1);
    cudaFuncSetAttribute(fp16_gemm_kernel<2, 2>,
                         cudaFuncAttributeMaxDynamicSharedMemorySize, GEMM_SMEM2);

    // 1. input + weight conversions
    convert_split_kernel<<<4096, 256>>>(q, qh, ql);
    wconv4_kernel<<<dim3(32, 32, 4), dim3(32, 32)>>>(Wq, Wqc, Wk, Wkc,
                                                     Wv, Wvc, Wo, Woc);

    // 2. projections
    dim3 ggrid(DD / 128, MM / 128);   // (8, 32)
    fp16_gemm_kernel<1, 2><<<ggrid, 256, GEMM_SMEM1>>>(qh, nullptr, Wqc, bq,
                                                       nullptr, Qh);
    fp16_gemm_kernel<1, 2><<<ggrid, 256, GEMM_SMEM1>>>(qh, nullptr, Wkc, bk,
                                                       nullptr, Kh);
    fp16_gemm_kernel<2, 2><<<ggrid, 256, GEMM_SMEM2>>>(qh, ql, Wvc, bv,
                                                       nullptr, Vh);

    // 3. attention
    flash_mma_kernel<<<dim3(SS / 128, HH, BB), 256, FLASH_SMEM>>>(Qh, Kh, Vh, Ath);

    // 4. output projection (single-pass A, fp32 out)
    fp16_gemm_kernel<1, 0><<<ggrid, 256, GEMM_SMEM1>>>(Ath, nullptr, Woc, bo,
                                                       (float*)d_out, nullptr);
}

// round 10
// speedup vs baseline: 5.8869x; 1.2700x over previous
#include <cuda_runtime.h>
#include <cuda_fp16.h>
#include <math.h>
#include <stdint.h>

// Problem constants
#define BB   2
#define SS   2048
#define DD   1024
#define HH   16
#define HS   64
#define MM   (BB * SS)     // 4096

// ---------------------------------------------------------------------------
// Scratch (device globals: allocation-free rule)
// ---------------------------------------------------------------------------
__device__ __half  g_qh[MM * DD];                    // input q fp16
__device__ __half  g_Qh[MM * DD];                    // projected Q
__device__ __half  g_Kh[MM * DD];                    // projected K
__device__ __half  g_Vh[MM * DD];                    // projected V
__device__ __half  g_Ath[MM * DD];                   // attention out
__device__ __half  g_Wq[DD * DD], g_Wk[DD * DD];     // transposed W
__device__ __half  g_Wv[DD * DD], g_Wo[DD * DD];

// ---------------------------------------------------------------------------
// Helpers (family-portable PTX only: ldmatrix / mma.sync / cp.async)
// ---------------------------------------------------------------------------
__device__ __forceinline__ uint32_t smem_to_u32(const void* p) {
    uint32_t a;
    asm("{ .reg .u64 t; cvta.to.shared.u64 t, %1; cvt.u32.u64 %0, t; }"
        : "=r"(a) : "l"(p));
    return a;
}
__device__ __forceinline__ void ldsm4(uint32_t (&r)[4], uint32_t addr) {
    asm volatile("ldmatrix.sync.aligned.m8n8.x4.shared.b16 {%0,%1,%2,%3}, [%4];"
                 : "=r"(r[0]), "=r"(r[1]), "=r"(r[2]), "=r"(r[3]) : "r"(addr));
}
__device__ __forceinline__ void ldsm4t(uint32_t (&r)[4], uint32_t addr) {
    asm volatile("ldmatrix.sync.aligned.m8n8.x4.trans.shared.b16 {%0,%1,%2,%3}, [%4];"
                 : "=r"(r[0]), "=r"(r[1]), "=r"(r[2]), "=r"(r[3]) : "r"(addr));
}
__device__ __forceinline__ void mma16816(float (&d)[4], const uint32_t (&a)[4],
                                         uint32_t b0, uint32_t b1) {
    asm volatile(
        "mma.sync.aligned.m16n8k16.row.col.f32.f16.f16.f32 "
        "{%0,%1,%2,%3}, {%4,%5,%6,%7}, {%8,%9}, {%0,%1,%2,%3};"
        : "+f"(d[0]), "+f"(d[1]), "+f"(d[2]), "+f"(d[3])
        : "r"(a[0]), "r"(a[1]), "r"(a[2]), "r"(a[3]), "r"(b0), "r"(b1));
}
#define CP_ASYNC16(dst, src) \
    asm volatile("cp.async.cg.shared.global [%0], [%1], 16;" :: "r"(dst), "l"(src))
#define CP_COMMIT() asm volatile("cp.async.commit_group;" ::: "memory")
#define CP_WAIT1()  asm volatile("cp.async.wait_group 1;" ::: "memory")
#define CP_WAIT0()  asm volatile("cp.async.wait_group 0;" ::: "memory")

__device__ __forceinline__ float fexp2(float x) {
    float r;
    asm("ex2.approx.f32 %0, %1;" : "=f"(r) : "f"(x));
    return r;
}

// SW128 swizzle of (row, 16B-chunk) -> byte offset (128B rows)
__device__ __forceinline__ uint32_t swoff(int row, int c) {
    return (uint32_t)(row * 128 + ((c ^ (row & 7)) << 4));
}

// ---------------------------------------------------------------------------
// convert q (fp32) -> fp16
// ---------------------------------------------------------------------------
__global__ void convert_h_kernel(const float* __restrict__ x,
                                 __half* __restrict__ xh)
{
    int i = blockIdx.x * blockDim.x + threadIdx.x;   // i indexes float4
    float4 v = ((const float4*)x)[i];
    __half2 a = __floats2half2_rn(v.x, v.y);
    __half2 b = __floats2half2_rn(v.z, v.w);
    uint32_t* p = (uint32_t*)xh + i * 2;
    p[0] = *(uint32_t*)&a;
    p[1] = *(uint32_t*)&b;
}

// ---------------------------------------------------------------------------
// fused weight transpose: 4x W[k][n] fp32 -> Wt fp16 [n][k] (blockIdx.z picks)
// ---------------------------------------------------------------------------
__global__ void wconv4_kernel(const float* __restrict__ W0, __half* __restrict__ T0,
                              const float* __restrict__ W1, __half* __restrict__ T1,
                              const float* __restrict__ W2, __half* __restrict__ T2,
                              const float* __restrict__ W3, __half* __restrict__ T3)
{
    const float* W = (blockIdx.z == 0) ? W0 : (blockIdx.z == 1) ? W1
                   : (blockIdx.z == 2) ? W2 : W3;
    __half* Wt     = (blockIdx.z == 0) ? T0 : (blockIdx.z == 1) ? T1
                   : (blockIdx.z == 2) ? T2 : T3;
    __shared__ float t[32][33];
    int k = blockIdx.y * 32 + threadIdx.y;
    int n = blockIdx.x * 32 + threadIdx.x;
    t[threadIdx.y][threadIdx.x] = W[k * DD + n];
    __syncthreads();
    int nn = blockIdx.x * 32 + threadIdx.y;
    int kk = blockIdx.y * 32 + threadIdx.x;
    Wt[nn * DD + kk] = __float2half(t[threadIdx.x][threadIdx.y]);
}

// ---------------------------------------------------------------------------
// fp16 single-pass mma.sync GEMM body: C = Ah·Bh^T + bias.
// OUTMODE=0: fp32 C.  OUTMODE=2: fp16 Ch.
// CTA 128x128, 8 warps (4m x 2n), KC=64, 2-stage cp.async.
// Uses blockIdx.x (n-tile) and blockIdx.y (m-tile) only.
// ---------------------------------------------------------------------------
#define KC        64
#define NCHUNK    (DD / KC)          // 16
#define TILE_B    16384              // 128 rows x 128 bytes
#define PADC      133
#define STG_B     (2 * TILE_B)       // AH + BH
#define OFF_BH    TILE_B
#define GEMM_SMEM 69632              // max(2*STG_B=65536, epilogue 68608)

template <int OUTMODE>
__device__ __forceinline__ void gemm_body(const __half* __restrict__ Ah,
                                          const __half* __restrict__ Bh,
                                          const float* __restrict__ bias,
                                          float* __restrict__ C,
                                          __half* __restrict__ Ch)
{
    extern __shared__ char smem[];
    const uint32_t sb = smem_to_u32(smem);
    const int tid  = threadIdx.x;
    const int wid  = tid >> 5;
    const int lane = tid & 31;

    const int n0 = blockIdx.x * 128;
    const int m0 = blockIdx.y * 128;

    const int m_base = (wid & 3) * 32;
    const int n_base = (wid >> 2) * 64;

    const __half* gAh = Ah + (size_t)m0 * DD;
    const __half* gBh = Bh + (size_t)n0 * DD;

    const int f_row = tid >> 3;
    const int f_c   = tid & 7;

    float acc[2][8][4];
#pragma unroll
    for (int i = 0; i < 2; i++)
#pragma unroll
        for (int j = 0; j < 8; j++)
#pragma unroll
            for (int e = 0; e < 4; e++) acc[i][j][e] = 0.f;

    const int lane15 = lane & 15, laneHi = lane >> 4;
    int aRow[2], bRow[4];
#pragma unroll
    for (int i = 0; i < 2; i++) aRow[i] = m_base + i * 16 + lane15;
#pragma unroll
    for (int j = 0; j < 4; j++) bRow[j] = n_base + j * 16 + lane15;

    auto fill_stage = [&](int chunk, int stg) {
        const uint32_t base = sb + (uint32_t)stg * STG_B;
        const int k0 = chunk * KC;
#pragma unroll
        for (int r4 = 0; r4 < 4; r4++) {
            const int row = f_row + r4 * 32;
            const uint32_t so = swoff(row, f_c);
            const size_t go = (size_t)row * DD + k0 + f_c * 8;
            CP_ASYNC16(base + so, gAh + go);
            CP_ASYNC16(base + OFF_BH + so, gBh + go);
        }
    };

    fill_stage(0, 0);
    CP_COMMIT();

    for (int c = 0; c < NCHUNK; c++) {
        if (c + 1 < NCHUNK) {
            fill_stage(c + 1, (c + 1) & 1);
            CP_COMMIT();
            CP_WAIT1();
        } else {
            CP_WAIT0();
        }
        __syncthreads();

        const uint32_t base = sb + (uint32_t)(c & 1) * STG_B;

#pragma unroll
        for (int ks = 0; ks < 4; ks++) {
            const int ch = ks * 2 + laneHi;
            uint32_t ah[2][4], bh[4][4];
#pragma unroll
            for (int i = 0; i < 2; i++) {
                const uint32_t ro = (uint32_t)(aRow[i] * 128);
                const uint32_t co = (uint32_t)((ch ^ (aRow[i] & 7)) << 4);
                ldsm4(ah[i], base + ro + co);
            }
#pragma unroll
            for (int j = 0; j < 4; j++) {
                const uint32_t ro = (uint32_t)(bRow[j] * 128);
                const uint32_t co = (uint32_t)((ch ^ (bRow[j] & 7)) << 4);
                ldsm4(bh[j], base + OFF_BH + ro + co);
            }
#pragma unroll
            for (int i = 0; i < 2; i++)
#pragma unroll
                for (int j = 0; j < 4; j++) {
                    mma16816(acc[i][2*j],   ah[i], bh[j][0], bh[j][2]);
                    mma16816(acc[i][2*j+1], ah[i], bh[j][1], bh[j][3]);
                }
        }
        __syncthreads();
    }

    // ---- epilogue via padded smem tile ----
    float* ts = (float*)smem;
    float* sbias = (float*)smem + 128 * PADC;
    if (tid < 128) sbias[tid] = bias[n0 + tid];

    const int cr = lane >> 2, cc = (lane & 3) * 2;
#pragma unroll
    for (int i = 0; i < 2; i++) {
        const int r0 = m_base + i * 16 + cr;
#pragma unroll
        for (int j = 0; j < 8; j++) {
            const int cn = n_base + j * 8 + cc;
            ts[r0 * PADC + cn]           = acc[i][j][0];
            ts[r0 * PADC + cn + 1]       = acc[i][j][1];
            ts[(r0 + 8) * PADC + cn]     = acc[i][j][2];
            ts[(r0 + 8) * PADC + cn + 1] = acc[i][j][3];
        }
    }
    __syncthreads();

    if (OUTMODE == 0) {
#pragma unroll 4
        for (int it = 0; it < 64; it++) {
            const int idx = it * 256 + tid;
            const int m = idx >> 7, n = idx & 127;
            C[(size_t)(m0 + m) * DD + n0 + n] = ts[m * PADC + n] + sbias[n];
        }
    } else {
#pragma unroll 4
        for (int it = 0; it < 32; it++) {
            const int idx = it * 256 + tid;
            const int m = idx >> 6, n = (idx & 63) * 2;
            float x = ts[m * PADC + n]     + sbias[n];
            float y = ts[m * PADC + n + 1] + sbias[n + 1];
            const size_t o = (size_t)(m0 + m) * DD + n0 + n;
            __half2 h = __floats2half2_rn(x, y);
            *(uint32_t*)(Ch + o) = *(uint32_t*)&h;
        }
    }
}

// Fused Q/K/V projection: blockIdx.z selects weight/bias/output.
__global__ __launch_bounds__(256)
void gemm_qkv_kernel(const __half* __restrict__ Ah,
                     const __half* __restrict__ Wq, const __half* __restrict__ Wk,
                     const __half* __restrict__ Wv,
                     const float* __restrict__ bq, const float* __restrict__ bk,
                     const float* __restrict__ bv,
                     __half* __restrict__ Qh, __half* __restrict__ Kh,
                     __half* __restrict__ Vh)
{
    const __half* B   = (blockIdx.z == 0) ? Wq : (blockIdx.z == 1) ? Wk : Wv;
    const float* bias = (blockIdx.z == 0) ? bq : (blockIdx.z == 1) ? bk : bv;
    __half* Ch        = (blockIdx.z == 0) ? Qh : (blockIdx.z == 1) ? Kh : Vh;
    gemm_body<2>(Ah, B, bias, nullptr, Ch);
}

// Output projection: fp32 out.
__global__ __launch_bounds__(256)
void gemm_o_kernel(const __half* __restrict__ Ah,
                   const __half* __restrict__ Wo,
                   const float* __restrict__ bo,
                   float* __restrict__ C)
{
    gemm_body<0>(Ah, Wo, bo, C, nullptr);
}

// ---------------------------------------------------------------------------
// Causal flash attention on mma.sync, single-pass everywhere.
// QK = Qh·Kh; PV = Ph·Vh. BQ=BKV=128, 256 threads (8 warps x m16).
// smem: Qh 16KB + 2 KV stages x (Kh,Vh 16KB each) = 80 KB -> occ 2.
// ---------------------------------------------------------------------------
#define FQH   0
#define FKH   0
#define FVH   16384
#define FSTG(s) (16384 + (s) * 32768)
#define FLASH_SMEM 81920
#define SCL   0.18033688011112042f   /* 0.125 * log2(e) */

__global__ __launch_bounds__(256)
void flash_mma_kernel(const __half* __restrict__ Qh_,
                      const __half* __restrict__ Kh_,
                      const __half* __restrict__ Vh_,
                      __half* __restrict__ Oh)
{
    extern __shared__ char smem[];
    const uint32_t sb = smem_to_u32(smem);
    const int tid  = threadIdx.x;
    const int wid  = tid >> 5;
    const int lane = tid & 31;
    const int lane15 = lane & 15, laneHi = lane >> 4;
    const int cr = lane >> 2, cc = (lane & 3) * 2;

    const int qt = (int)gridDim.x - 1 - (int)blockIdx.x;   // heavy-first
    const int qb = qt * 128;
    const int h  = blockIdx.y;
    const int b  = blockIdx.z;

    const size_t hoff = (size_t)h * HS;
    const __half* gQh = Qh_ + (size_t)(b * SS + qb) * DD + hoff;
    const __half* gKh = Kh_ + (size_t)(b * SS) * DD + hoff;
    const __half* gVh = Vh_ + (size_t)(b * SS) * DD + hoff;

    const int f_row = tid >> 3;     // 0..31
    const int f_c   = tid & 7;

    // fill Q (once)
#pragma unroll
    for (int r4 = 0; r4 < 4; r4++) {
        const int row = f_row + r4 * 32;
        const uint32_t so = swoff(row, f_c);
        CP_ASYNC16(sb + FQH + so, gQh + (size_t)row * DD + f_c * 8);
    }
    auto fill_kv = [&](int kb, int st) {
        const uint32_t base = sb + FSTG(st);
#pragma unroll
        for (int r4 = 0; r4 < 4; r4++) {
            const int row = f_row + r4 * 32;
            const uint32_t so = swoff(row, f_c);
            const size_t go = (size_t)(kb + row) * DD + f_c * 8;
            CP_ASYNC16(base + FKH + so, gKh + go);
            CP_ASYNC16(base + FVH + so, gVh + go);
        }
    };
    fill_kv(0, 0);
    CP_COMMIT();

    uint32_t qfh[4][4];
    float o[8][4];
#pragma unroll
    for (int j = 0; j < 8; j++)
#pragma unroll
        for (int e = 0; e < 4; e++) o[j][e] = 0.f;
    float m0 = -INFINITY, m1 = -INFINITY, l0 = 0.f, l1 = 0.f;

    // V ldsm row (per lane, fixed across loop)
    const int vrow_lane = (lane & 7) + 8 * ((lane >> 3) & 1);
    const int vchunk_hi = lane >> 4;     // +0/+1 chunk

    for (int c = 0; c <= qt; c++) {
        if (c < qt) {
            fill_kv((c + 1) * 128, (c + 1) & 1);
            CP_COMMIT();
            CP_WAIT1();
        } else {
            CP_WAIT0();
        }
        __syncthreads();

        if (c == 0) {
            // Q fragments: row-major A frags, register resident
            const int qr = wid * 16 + lane15;
            const uint32_t ro = (uint32_t)(qr * 128);
            const int sw = qr & 7;
#pragma unroll
            for (int ks = 0; ks < 4; ks++) {
                const int ch = ks * 2 + laneHi;
                ldsm4(qfh[ks], sb + FQH + ro + (uint32_t)((ch ^ sw) << 4));
            }
        }

        const uint32_t base = sb + FSTG(c & 1);

        // ---- scores: Qh·Kh ----
        float acc[16][4];
#pragma unroll
        for (int j = 0; j < 16; j++)
#pragma unroll
            for (int e = 0; e < 4; e++) acc[j][e] = 0.f;

#pragma unroll
        for (int ks = 0; ks < 4; ks++) {
            const int ch = ks * 2 + laneHi;
#pragma unroll
            for (int j = 0; j < 8; j++) {
                const int br = j * 16 + lane15;
                const uint32_t off = (uint32_t)(br * 128 + ((ch ^ (br & 7)) << 4));
                uint32_t kh[4];
                ldsm4(kh, base + FKH + off);
                mma16816(acc[2*j],   qfh[ks], kh[0], kh[2]);
                mma16816(acc[2*j+1], qfh[ks], kh[1], kh[3]);
            }
        }

        // ---- causal mask (diagonal tile) ----
        if (c == qt) {
            const int qr0 = wid * 16 + cr;
#pragma unroll
            for (int j = 0; j < 16; j++) {
                const int col = j * 8 + cc;
                if (col     > qr0)     acc[j][0] = -INFINITY;
                if (col + 1 > qr0)     acc[j][1] = -INFINITY;
                if (col     > qr0 + 8) acc[j][2] = -INFINITY;
                if (col + 1 > qr0 + 8) acc[j][3] = -INFINITY;
            }
        }

        // ---- online softmax (fp32, scale folded into exp2) ----
        float mx0 = -INFINITY, mx1 = -INFINITY;
#pragma unroll
        for (int j = 0; j < 16; j++) {
            mx0 = fmaxf(mx0, fmaxf(acc[j][0], acc[j][1]));
            mx1 = fmaxf(mx1, fmaxf(acc[j][2], acc[j][3]));
        }
        mx0 = fmaxf(mx0, __shfl_xor_sync(0xffffffffu, mx0, 1));
        mx0 = fmaxf(mx0, __shfl_xor_sync(0xffffffffu, mx0, 2));
        mx1 = fmaxf(mx1, __shfl_xor_sync(0xffffffffu, mx1, 1));
        mx1 = fmaxf(mx1, __shfl_xor_sync(0xffffffffu, mx1, 2));
        const float mn0 = fmaxf(m0, mx0);
        const float mn1 = fmaxf(m1, mx1);
        const float a0 = fexp2((m0 - mn0) * SCL);
        const float a1 = fexp2((m1 - mn1) * SCL);
        m0 = mn0; m1 = mn1;
        float rs0 = 0.f, rs1 = 0.f;
#pragma unroll
        for (int j = 0; j < 16; j++) {
            acc[j][0] = fexp2((acc[j][0] - mn0) * SCL);
            acc[j][1] = fexp2((acc[j][1] - mn0) * SCL);
            acc[j][2] = fexp2((acc[j][2] - mn1) * SCL);
            acc[j][3] = fexp2((acc[j][3] - mn1) * SCL);
            rs0 += acc[j][0] + acc[j][1];
            rs1 += acc[j][2] + acc[j][3];
        }
        rs0 += __shfl_xor_sync(0xffffffffu, rs0, 1);
        rs0 += __shfl_xor_sync(0xffffffffu, rs0, 2);
        rs1 += __shfl_xor_sync(0xffffffffu, rs1, 1);
        rs1 += __shfl_xor_sync(0xffffffffu, rs1, 2);
        l0 = l0 * a0 + rs0;
        l1 = l1 * a1 + rs1;
#pragma unroll
        for (int j = 0; j < 8; j++) {
            o[j][0] *= a0; o[j][1] *= a0;
            o[j][2] *= a1; o[j][3] *= a1;
        }

        // ---- PV: Ph·Vh (single pass), P frags straight from score regs ----
#pragma unroll
        for (int t = 0; t < 8; t++) {
            uint32_t Ap[4];
            __half2 p0 = __floats2half2_rn(acc[2*t][0],   acc[2*t][1]);
            __half2 p1 = __floats2half2_rn(acc[2*t][2],   acc[2*t][3]);
            __half2 p2 = __floats2half2_rn(acc[2*t+1][0], acc[2*t+1][1]);
            __half2 p3 = __floats2half2_rn(acc[2*t+1][2], acc[2*t+1][3]);
            Ap[0] = *(uint32_t*)&p0;  Ap[1] = *(uint32_t*)&p1;
            Ap[2] = *(uint32_t*)&p2;  Ap[3] = *(uint32_t*)&p3;
            const int vr = t * 16 + vrow_lane;
            const uint32_t tro = (uint32_t)(vr * 128);
            const int tsw = vr & 7;
#pragma unroll
            for (int nt = 0; nt < 4; nt++) {
                const int chv = nt * 2 + vchunk_hi;
                const uint32_t voff = tro + (uint32_t)((chv ^ tsw) << 4);
                uint32_t vh[4];
                ldsm4t(vh, base + FVH + voff);
                mma16816(o[2*nt],   Ap, vh[0], vh[1]);
                mma16816(o[2*nt+1], Ap, vh[2], vh[3]);
            }
        }
        __syncthreads();
    }

    // ---- epilogue: normalize + fp16, natural layout ----
    const float inv0 = 1.f / l0;
    const float inv1 = 1.f / l1;
    const int q0 = qb + wid * 16 + cr;
    const size_t r0o = (size_t)(b * SS + q0) * DD + (size_t)h * HS;
    const size_t r1o = r0o + (size_t)8 * DD;
#pragma unroll
    for (int j = 0; j < 8; j++) {
        const int d = j * 8 + cc;
        __half2 h0 = __floats2half2_rn(o[j][0] * inv0, o[j][1] * inv0);
        __half2 h1 = __floats2half2_rn(o[j][2] * inv1, o[j][3] * inv1);
        *(uint32_t*)(Oh + r0o + d) = *(uint32_t*)&h0;
        *(uint32_t*)(Oh + r1o + d) = *(uint32_t*)&h1;
    }
}

// ---------------------------------------------------------------------------
extern "C" void kernel_launch(void* const* d_in, const int* in_sizes, int n_in,
                              void* d_out, int out_size)
{
    const float* q  = (const float*)d_in[0];
    const float* Wq = (const float*)d_in[1];
    const float* bq = (const float*)d_in[2];
    const float* Wk = (const float*)d_in[3];
    const float* bk = (const float*)d_in[4];
    const float* Wv = (const float*)d_in[5];
    const float* bv = (const float*)d_in[6];
    const float* Wo = (const float*)d_in[7];
    const float* bo = (const float*)d_in[8];

    __half *qh, *Qh, *Kh, *Vh, *Ath;
    __half *Wqc, *Wkc, *Wvc, *Woc;
    cudaGetSymbolAddress((void**)&qh,  g_qh);
    cudaGetSymbolAddress((void**)&Qh,  g_Qh);
    cudaGetSymbolAddress((void**)&Kh,  g_Kh);
    cudaGetSymbolAddress((void**)&Vh,  g_Vh);
    cudaGetSymbolAddress((void**)&Ath, g_Ath);
    cudaGetSymbolAddress((void**)&Wqc, g_Wq);
    cudaGetSymbolAddress((void**)&Wkc, g_Wk);
    cudaGetSymbolAddress((void**)&Wvc, g_Wv);
    cudaGetSymbolAddress((void**)&Woc, g_Wo);

    cudaFuncSetAttribute(flash_mma_kernel,
                         cudaFuncAttributeMaxDynamicSharedMemorySize, FLASH_SMEM);
    cudaFuncSetAttribute(gemm_qkv_kernel,
                         cudaFuncAttributeMaxDynamicSharedMemorySize, GEMM_SMEM);
    cudaFuncSetAttribute(gemm_o_kernel,
                         cudaFuncAttributeMaxDynamicSharedMemorySize, GEMM_SMEM);

    // 1. input + weight conversions
    convert_h_kernel<<<4096, 256>>>(q, qh);
    wconv4_kernel<<<dim3(32, 32, 4), dim3(32, 32)>>>(Wq, Wqc, Wk, Wkc,
                                                     Wv, Wvc, Wo, Woc);

    // 2. fused Q/K/V projections (one launch, 768 CTAs)
    gemm_qkv_kernel<<<dim3(DD / 128, MM / 128, 3), 256, GEMM_SMEM>>>(
        qh, Wqc, Wkc, Wvc, bq, bk, bv, Qh, Kh, Vh);

    // 3. attention
    flash_mma_kernel<<<dim3(SS / 128, HH, BB), 256, FLASH_SMEM>>>(Qh, Kh, Vh, Ath);

    // 4. output projection (fp32 out)
    gemm_o_kernel<<<dim3(DD / 128, MM / 128), 256, GEMM_SMEM>>>(Ath, Woc, bo,
                                                                (float*)d_out);
}